// round 13
// baseline (speedup 1.0000x reference)
#include <cuda_runtime.h>
#include <cuda_bf16.h>
#include <math.h>
#include <stdint.h>

// Problem constants
#define TT      2048
#define DM      6144
#define NH      48
#define NKV     8
#define HD      128
#define QKV_N   8192
#define KV_OFF  DM
#define V_OFF   (DM + NKV*HD)
#define REP     (NH / NKV)
#define CLAMP_V 8.0f

// Scratch (static device globals)
__device__ float g_qkv[(size_t)TT * QKV_N];
__device__ float g_attn[(size_t)TT * DM];
__device__ float g_xp[(size_t)TT * DM];
__device__ float g_wqkvp[(size_t)QKV_N * DM];
__device__ float g_woutp[(size_t)DM * DM];
__device__ float g_invf[64];

// ===========================================================================
// Helpers
// ===========================================================================
__device__ __forceinline__ uint32_t smem_to_u32(const void* p) {
    uint32_t a;
    asm("{ .reg .u64 t; cvta.to.shared.u64 t, %1; cvt.u32.u64 %0, t; }"
        : "=r"(a) : "l"(p));
    return a;
}
__device__ __forceinline__ void cp16(uint32_t s, const void* g) {
    asm volatile("cp.async.cg.shared.global [%0], [%1], 16;"
                 :: "r"(s), "l"(g) : "memory");
}
__device__ __forceinline__ float ftf32(float x) {
    uint32_t o, i = __float_as_uint(x);
    asm("cvt.rna.tf32.f32 %0, %1;" : "=r"(o) : "r"(i));
    return __uint_as_float(o);
}
__device__ __forceinline__ void mma8(float* d, const uint32_t* a, const uint32_t* b) {
    asm volatile(
        "mma.sync.aligned.m16n8k8.row.col.f32.tf32.tf32.f32 "
        "{%0,%1,%2,%3}, {%4,%5,%6,%7}, {%8,%9}, {%0,%1,%2,%3};"
        : "+f"(d[0]), "+f"(d[1]), "+f"(d[2]), "+f"(d[3])
        : "r"(a[0]), "r"(a[1]), "r"(a[2]), "r"(a[3]), "r"(b[0]), "r"(b[1]));
}
__device__ __forceinline__ void mma16bf(float* d, const uint32_t* a, const uint32_t* b) {
    asm volatile(
        "mma.sync.aligned.m16n8k16.row.col.f32.bf16.bf16.f32 "
        "{%0,%1,%2,%3}, {%4,%5,%6,%7}, {%8,%9}, {%0,%1,%2,%3};"
        : "+f"(d[0]), "+f"(d[1]), "+f"(d[2]), "+f"(d[3])
        : "r"(a[0]), "r"(a[1]), "r"(a[2]), "r"(a[3]), "r"(b[0]), "r"(b[1]));
}
__device__ __forceinline__ uint32_t packsplit(float x, float y, uint32_t& lo) {
    __nv_bfloat16 hx = __float2bfloat16(x);
    __nv_bfloat16 hy = __float2bfloat16(y);
    float rx = x - __bfloat162float(hx);
    float ry = y - __bfloat162float(hy);
    __nv_bfloat16 lx = __float2bfloat16(rx);
    __nv_bfloat16 ly = __float2bfloat16(ry);
    lo = ((uint32_t)__bfloat16_as_ushort(ly) << 16) | __bfloat16_as_ushort(lx);
    return ((uint32_t)__bfloat16_as_ushort(hy) << 16) | __bfloat16_as_ushort(hx);
}
__device__ __forceinline__ float clmp(float v) {
    return fminf(fmaxf(v, -CLAMP_V), CLAMP_V);
}

// ===========================================================================
// inv_freq table
// ===========================================================================
__global__ void init_invf_kernel()
{
    int i = threadIdx.x;
    g_invf[i] = (float)pow(500000.0, -(double)i / 64.0);
}

// ===========================================================================
// Permute (within-16 grouping: k=8a+4d+c -> pos=4c+2d+a) + rna-tf32 round.
// One thread per 16 floats; coalesced float4 I/O.
// pos 4c..4c+3 = [k(c), k(c+8), k(c+4), k(c+12)]
// ===========================================================================
__global__ __launch_bounds__(256)
void perm_round_kernel(const float4* __restrict__ src, float4* __restrict__ dst, int n16)
{
    int g = blockIdx.x * blockDim.x + threadIdx.x;
    if (g < n16) {
        float4 i0 = src[4 * g];       // k 0..3
        float4 i1 = src[4 * g + 1];   // k 4..7
        float4 i2 = src[4 * g + 2];   // k 8..11
        float4 i3 = src[4 * g + 3];   // k 12..15
        dst[4 * g]     = make_float4(ftf32(i0.x), ftf32(i2.x), ftf32(i1.x), ftf32(i3.x));
        dst[4 * g + 1] = make_float4(ftf32(i0.y), ftf32(i2.y), ftf32(i1.y), ftf32(i3.y));
        dst[4 * g + 2] = make_float4(ftf32(i0.z), ftf32(i2.z), ftf32(i1.z), ftf32(i3.z));
        dst[4 * g + 3] = make_float4(ftf32(i0.w), ftf32(i2.w), ftf32(i1.w), ftf32(i3.w));
    }
}

// ===========================================================================
// tf32 mma.sync GEMM on K-PERMUTED (16-group) pre-rounded operands.
// CTA tile 128x128, 256 threads (8 warps, 64x32 warp tile), 2 CTAs/SM,
// 3-stage cp.async, one sync/iter. LDS.128 fragment loads: one float4 per
// thread covers two ks-steps (.x/.z = even ks, .y/.w = odd ks).
// Swizzle sw(row) = ((row&1)<<2) ^ (row&2) at float4-unit granularity.
// mode 1: fused RoPE+clamp epilogue (writes NORMAL column order).
// ===========================================================================
#define TSZ  (128 * 32)
#define GEMM_SMEM_BYTES (6 * TSZ * 4)

__global__ __launch_bounds__(256, 2)
void gemm_mma(const float* __restrict__ A, const float* __restrict__ B,
              float* __restrict__ C, int N, int K, int mode)
{
    extern __shared__ float sm[];
    const int tid  = threadIdx.x;
    const int wid  = tid >> 5, lane = tid & 31;
    const int wm   = (wid >> 2) * 64;
    const int wn   = (wid & 3) * 32;
    const int gr   = lane >> 2, tc = lane & 3;
    const int bm   = blockIdx.y * 128, bn = blockIdx.x * 128;

    const int ldr = tid >> 3;               // 0..31
    const int ldu = tid & 7;                // float4 unit 0..7

    const uint32_t sbase = smem_to_u32(sm);
    const int NS = K / 32;

    float acc[4][4][4];
#pragma unroll
    for (int i = 0; i < 4; i++)
#pragma unroll
        for (int j = 0; j < 4; j++)
#pragma unroll
            for (int r = 0; r < 4; r++) acc[i][j][r] = 0.f;

    // writer swizzle: sw(row) = ((row&1)<<2) ^ (row&2)
    const int lsw = ((ldr & 1) << 2) ^ (ldr & 2);
    const int lu  = (ldu ^ lsw) << 2;

    auto loadTiles = [&](int k0, int st) {
#pragma unroll
        for (int v = 0; v < 4; v++) {
            int row = ldr + v * 32;
            uint32_t sa = sbase + (uint32_t)(st * TSZ + row * 32 + lu) * 4;
            cp16(sa, A + (size_t)(bm + row) * K + k0 + ldu * 4);
            uint32_t sb = sbase + (uint32_t)(3 * TSZ + st * TSZ + row * 32 + lu) * 4;
            cp16(sb, B + (size_t)(bn + row) * K + k0 + ldu * 4);
        }
        asm volatile("cp.async.commit_group;" ::: "memory");
    };

    loadTiles(0, 0);
    loadTiles(32, 1);

    // reader swizzle (row == gr mod 8, and sw uses row&3 == gr&3)
    const int asw = ((gr & 1) << 2) ^ (gr & 2);
    int arow[4], brow[4];
#pragma unroll
    for (int i = 0; i < 4; i++) arow[i] = (wm + i * 16 + gr) * 32;
#pragma unroll
    for (int j = 0; j < 4; j++) brow[j] = (wn + j * 8 + gr) * 32;
    const int uof0 = ((0 + tc) ^ asw) << 2;   // 16-block 0
    const int uof1 = ((4 + tc) ^ asw) << 2;   // 16-block 1

    int st = 0;
    for (int s = 0; s < NS; s++) {
        asm volatile("cp.async.wait_group 1;" ::: "memory");
        __syncthreads();

        int nst = st + 2; if (nst >= 3) nst -= 3;
        if (s + 2 < NS) loadTiles((s + 2) * 32, nst);
        else asm volatile("cp.async.commit_group;" ::: "memory");

        const float* As_ = sm + st * TSZ;
        const float* Bs_ = sm + 3 * TSZ + st * TSZ;

#pragma unroll
        for (int blk = 0; blk < 2; blk++) {
            const int uof = blk ? uof1 : uof0;
            float4 a0[4], a1[4], bv[4];
#pragma unroll
            for (int i = 0; i < 4; i++) {
                a0[i] = *(const float4*)(As_ + arow[i] + uof);
                a1[i] = *(const float4*)(As_ + arow[i] + 256 + uof);
            }
#pragma unroll
            for (int j = 0; j < 4; j++)
                bv[j] = *(const float4*)(Bs_ + brow[j] + uof);

            // ks even (.x/.z)
            {
                uint32_t a[4][4], b[4][2];
#pragma unroll
                for (int i = 0; i < 4; i++) {
                    a[i][0] = __float_as_uint(a0[i].x);
                    a[i][1] = __float_as_uint(a1[i].x);
                    a[i][2] = __float_as_uint(a0[i].z);
                    a[i][3] = __float_as_uint(a1[i].z);
                }
#pragma unroll
                for (int j = 0; j < 4; j++) {
                    b[j][0] = __float_as_uint(bv[j].x);
                    b[j][1] = __float_as_uint(bv[j].z);
                }
#pragma unroll
                for (int i = 0; i < 4; i++)
#pragma unroll
                    for (int j = 0; j < 4; j++)
                        mma8(acc[i][j], a[i], b[j]);
            }
            // ks odd (.y/.w)
            {
                uint32_t a[4][4], b[4][2];
#pragma unroll
                for (int i = 0; i < 4; i++) {
                    a[i][0] = __float_as_uint(a0[i].y);
                    a[i][1] = __float_as_uint(a1[i].y);
                    a[i][2] = __float_as_uint(a0[i].w);
                    a[i][3] = __float_as_uint(a1[i].w);
                }
#pragma unroll
                for (int j = 0; j < 4; j++) {
                    b[j][0] = __float_as_uint(bv[j].y);
                    b[j][1] = __float_as_uint(bv[j].w);
                }
#pragma unroll
                for (int i = 0; i < 4; i++)
#pragma unroll
                    for (int j = 0; j < 4; j++)
                        mma8(acc[i][j], a[i], b[j]);
            }
        }

        if (++st == 3) st = 0;
    }

    // Epilogue (normal column order; RoPE pairs when mode==1)
#pragma unroll
    for (int i = 0; i < 4; i++) {
#pragma unroll
        for (int j = 0; j < 4; j++) {
            int r = bm + wm + i * 16 + gr;
            int c = bn + wn + j * 8 + tc * 2;
            float2 v0 = make_float2(acc[i][j][0], acc[i][j][1]);
            float2 v1 = make_float2(acc[i][j][2], acc[i][j][3]);
            if (mode == 1) {
                if (c < V_OFF) {
                    int i64 = (c >> 1) & 63;
                    float inv = g_invf[i64];
                    float s0, c0;
                    sincosf((float)r * inv, &s0, &c0);
                    float a0 = v0.x, b0 = v0.y;
                    v0.x = clmp(a0 * c0 - b0 * s0);
                    v0.y = clmp(a0 * s0 + b0 * c0);
                    float s1, c1;
                    sincosf((float)(r + 8) * inv, &s1, &c1);
                    float a1 = v1.x, b1 = v1.y;
                    v1.x = clmp(a1 * c1 - b1 * s1);
                    v1.y = clmp(a1 * s1 + b1 * c1);
                } else {
                    v0.x = clmp(v0.x); v0.y = clmp(v0.y);
                    v1.x = clmp(v1.x); v1.y = clmp(v1.y);
                }
            }
            *(float2*)&C[(size_t)r * N + c]       = v0;
            *(float2*)&C[(size_t)(r + 8) * N + c] = v1;
        }
    }
}

// ===========================================================================
// Tensor-core flash attention (R12 core; output written in the NEW 16-group
// K-permutation + rna-rounded, feeding the out-proj GEMM).
// ===========================================================================
#define A_QH   0
#define A_QL   34816
#define A_KH   69632
#define A_KL   87040
#define A_VTH  104448
#define A_VTL  122880
#define A_SS   141312
#define A_PHB  176128
#define A_PLB  194560
#define A_VS   176128
#define A_STAT 212992
#define ATT_SMEM 215552

__global__ __launch_bounds__(256, 1)
void attn_mma_kernel(float* __restrict__ out)
{
    extern __shared__ char smem[];
    uint32_t* QHw = (uint32_t*)(smem + A_QH);
    uint32_t* QLw = (uint32_t*)(smem + A_QL);
    uint32_t* KHw = (uint32_t*)(smem + A_KH);
    uint32_t* KLw = (uint32_t*)(smem + A_KL);
    uint32_t* VTH = (uint32_t*)(smem + A_VTH);
    uint32_t* VTL = (uint32_t*)(smem + A_VTL);
    float*    SS  = (float*)(smem + A_SS);
    uint32_t* PHB = (uint32_t*)(smem + A_PHB);
    uint32_t* PLB = (uint32_t*)(smem + A_PLB);
    float*    VS  = (float*)(smem + A_VS);
    float* rowM = (float*)(smem + A_STAT);
    float* rowL = rowM + 128;
    float* rowA = rowL + 128;
    float* PPAR = rowA + 128;

    const int qb   = gridDim.x - 1 - blockIdx.x;
    const int h    = blockIdx.y;
    const int kh   = h / REP;
    const int tid  = threadIdx.x;
    const int wid  = tid >> 5, lane = tid & 31;
    const int gr   = lane >> 2, tc = lane & 3;
    const int m0   = (wid >> 1) * 32;
    const int wn   = (wid & 1) * 32;
    const int nv   = (wid & 1) * 64;
    const float scale = 0.088388347648318447f;

    {
        const float* qg = g_qkv + (size_t)(qb * 128) * QKV_N + h * HD;
#pragma unroll
        for (int i = 0; i < 16; i++) {
            int f = tid + i * 256;
            int r = f >> 5;
            int c = (f & 31) * 4;
            float4 v = *(const float4*)(qg + (size_t)r * QKV_N + c);
            uint32_t l0, l1;
            uint32_t h0 = packsplit(v.x, v.y, l0);
            uint32_t h1 = packsplit(v.z, v.w, l1);
            QHw[r * 68 + c / 2]     = h0;
            QHw[r * 68 + c / 2 + 1] = h1;
            QLw[r * 68 + c / 2]     = l0;
            QLw[r * 68 + c / 2 + 1] = l1;
        }
    }
    if (tid < 128) { rowM[tid] = -1e30f; rowL[tid] = 0.f; }

    float o[2][8][4];
#pragma unroll
    for (int mi = 0; mi < 2; mi++)
#pragma unroll
        for (int j = 0; j < 8; j++)
#pragma unroll
            for (int r = 0; r < 4; r++) o[mi][j][r] = 0.f;

    const int nkt = 2 * qb + 2;
    for (int kt = 0; kt < nkt; kt++) {
        __syncthreads();

        {
            const float* kg = g_qkv + (size_t)(kt * 64) * QKV_N + KV_OFF + kh * HD;
            const float* vg = g_qkv + (size_t)(kt * 64) * QKV_N + V_OFF  + kh * HD;
#pragma unroll
            for (int i = 0; i < 8; i++) {
                int f = tid + i * 256;
                int r = f >> 5;
                int c = (f & 31) * 4;
                float4 kv = *(const float4*)(kg + (size_t)r * QKV_N + c);
                uint32_t l0, l1;
                uint32_t h0 = packsplit(kv.x, kv.y, l0);
                uint32_t h1 = packsplit(kv.z, kv.w, l1);
                KHw[r * 68 + c / 2]     = h0;
                KHw[r * 68 + c / 2 + 1] = h1;
                KLw[r * 68 + c / 2]     = l0;
                KLw[r * 68 + c / 2 + 1] = l1;
                float4 vv = *(const float4*)(vg + (size_t)r * QKV_N + c);
                VS[r * 133 + c + 0] = vv.x;
                VS[r * 133 + c + 1] = vv.y;
                VS[r * 133 + c + 2] = vv.z;
                VS[r * 133 + c + 3] = vv.w;
            }
        }
        __syncthreads();

        // Transpose V + bf16 split
#pragma unroll
        for (int i = 0; i < 16; i++) {
            int idx = tid + i * 256;
            int d = idx >> 5;
            int w = idx & 31;
            float v0 = VS[(2 * w) * 133 + d];
            float v1 = VS[(2 * w + 1) * 133 + d];
            uint32_t lo;
            uint32_t hi = packsplit(v0, v1, lo);
            VTH[d * 36 + w] = hi;
            VTL[d * 36 + w] = lo;
        }

        // S = Q K^T (bf16x3)
        float sacc[2][4][4];
#pragma unroll
        for (int mi = 0; mi < 2; mi++)
#pragma unroll
            for (int j = 0; j < 4; j++)
#pragma unroll
                for (int r = 0; r < 4; r++) sacc[mi][j][r] = 0.f;

#pragma unroll
        for (int ks = 0; ks < 8; ks++) {
            uint32_t ah[2][4], al[2][4];
#pragma unroll
            for (int mi = 0; mi < 2; mi++) {
                int base = (m0 + mi * 16 + gr) * 68 + ks * 8 + tc;
                ah[mi][0] = QHw[base];
                ah[mi][1] = QHw[base + 8 * 68];
                ah[mi][2] = QHw[base + 4];
                ah[mi][3] = QHw[base + 8 * 68 + 4];
                al[mi][0] = QLw[base];
                al[mi][1] = QLw[base + 8 * 68];
                al[mi][2] = QLw[base + 4];
                al[mi][3] = QLw[base + 8 * 68 + 4];
            }
            uint32_t bh[4][2], bl[4][2];
#pragma unroll
            for (int j = 0; j < 4; j++) {
                int base = (wn + j * 8 + gr) * 68 + ks * 8 + tc;
                bh[j][0] = KHw[base];
                bh[j][1] = KHw[base + 4];
                bl[j][0] = KLw[base];
                bl[j][1] = KLw[base + 4];
            }
#pragma unroll
            for (int mi = 0; mi < 2; mi++)
#pragma unroll
                for (int j = 0; j < 4; j++) {
                    mma16bf(sacc[mi][j], ah[mi], bh[j]);
                    mma16bf(sacc[mi][j], ah[mi], bl[j]);
                    mma16bf(sacc[mi][j], al[mi], bh[j]);
                }
        }

        const bool dg = (kt >= 2 * qb);
#pragma unroll
        for (int mi = 0; mi < 2; mi++) {
#pragma unroll
            for (int j = 0; j < 4; j++) {
                int rl0 = m0 + mi * 16 + gr;
                int cl  = wn + j * 8 + 2 * tc;
                float v0 = sacc[mi][j][0] * scale;
                float v1 = sacc[mi][j][1] * scale;
                float v2 = sacc[mi][j][2] * scale;
                float v3 = sacc[mi][j][3] * scale;
                if (dg) {
                    int rg0 = qb * 128 + rl0;
                    int cg  = kt * 64 + cl;
                    if (cg     > rg0)     v0 = -1e30f;
                    if (cg + 1 > rg0)     v1 = -1e30f;
                    if (cg     > rg0 + 8) v2 = -1e30f;
                    if (cg + 1 > rg0 + 8) v3 = -1e30f;
                }
                *(float2*)&SS[rl0 * 68 + cl]       = make_float2(v0, v1);
                *(float2*)&SS[(rl0 + 8) * 68 + cl] = make_float2(v2, v3);
            }
        }
        __syncthreads();

        // online softmax, 256 threads; write P as packed bf16x2 hi/lo
        {
            const int r  = tid & 127;
            const int hf = tid >> 7;
            const float4* srow = (const float4*)(SS + r * 68) + hf * 8;
            float4 sv[8];
            float pm = -1e30f;
#pragma unroll
            for (int jj = 0; jj < 8; jj++) {
                sv[jj] = srow[jj];
                pm = fmaxf(pm, fmaxf(fmaxf(sv[jj].x, sv[jj].y), fmaxf(sv[jj].z, sv[jj].w)));
            }
            PPAR[tid] = pm;
            __syncthreads();
            float mOld = rowM[r];
            float m = fmaxf(mOld, fmaxf(PPAR[r], PPAR[r + 128]));
            float l = 0.f;
            uint32_t* phh = PHB + r * 36 + hf * 16;
            uint32_t* pll = PLB + r * 36 + hf * 16;
#pragma unroll
            for (int jj = 0; jj < 8; jj++) {
                float p0 = __expf(sv[jj].x - m);
                float p1 = __expf(sv[jj].y - m);
                float p2 = __expf(sv[jj].z - m);
                float p3 = __expf(sv[jj].w - m);
                l += (p0 + p1) + (p2 + p3);
                uint32_t lo0, lo1;
                uint32_t h0 = packsplit(p0, p1, lo0);
                uint32_t h1 = packsplit(p2, p3, lo1);
                phh[2 * jj]     = h0;
                phh[2 * jj + 1] = h1;
                pll[2 * jj]     = lo0;
                pll[2 * jj + 1] = lo1;
            }
            PPAR[tid] = l;
            __syncthreads();
            if (tid < 128) {
                float alpha = __expf(mOld - m);
                rowL[r] = rowL[r] * alpha + (PPAR[r] + PPAR[r + 128]);
                rowM[r] = m;
                rowA[r] = alpha;
            }
        }
        __syncthreads();

        // O = alpha*O + P V  (bf16x3)
#pragma unroll
        for (int mi = 0; mi < 2; mi++) {
            float am0 = rowA[m0 + mi * 16 + gr];
            float am1 = rowA[m0 + mi * 16 + gr + 8];
#pragma unroll
            for (int j = 0; j < 8; j++) {
                o[mi][j][0] *= am0; o[mi][j][1] *= am0;
                o[mi][j][2] *= am1; o[mi][j][3] *= am1;
            }
        }
#pragma unroll
        for (int ks = 0; ks < 4; ks++) {
            uint32_t aph[2][4], apl[2][4];
#pragma unroll
            for (int mi = 0; mi < 2; mi++) {
                int base = (m0 + mi * 16 + gr) * 36 + ks * 8 + tc;
                aph[mi][0] = PHB[base];
                aph[mi][1] = PHB[base + 8 * 36];
                aph[mi][2] = PHB[base + 4];
                aph[mi][3] = PHB[base + 8 * 36 + 4];
                apl[mi][0] = PLB[base];
                apl[mi][1] = PLB[base + 8 * 36];
                apl[mi][2] = PLB[base + 4];
                apl[mi][3] = PLB[base + 8 * 36 + 4];
            }
#pragma unroll
            for (int j = 0; j < 8; j++) {
                int base = (nv + j * 8 + gr) * 36 + ks * 8 + tc;
                uint32_t bh[2], bl[2];
                bh[0] = VTH[base];
                bh[1] = VTH[base + 4];
                bl[0] = VTL[base];
                bl[1] = VTL[base + 4];
#pragma unroll
                for (int mi = 0; mi < 2; mi++) {
                    mma16bf(o[mi][j], aph[mi], bh);
                    mma16bf(o[mi][j], aph[mi], bl);
                    mma16bf(o[mi][j], apl[mi], bh);
                }
            }
        }
    }

    // normalize + rna-round + 16-group K-PERMUTED store
    // col 2tc within 8-group j: k = 8*(j&1) + 2tc -> pos = 8*(tc&1)+2*(tc>>1)+(j&1);
    // col 2tc+1 -> pos+4. 16-group base = nv + (j>>1)*16.
    const int pb = ((tc & 1) << 3) + ((tc >> 1) << 1);
#pragma unroll
    for (int mi = 0; mi < 2; mi++) {
        int rl0 = m0 + mi * 16 + gr;
        float inv0 = 1.f / rowL[rl0];
        float inv1 = 1.f / rowL[rl0 + 8];
        int rg0 = qb * 128 + rl0;
#pragma unroll
        for (int j = 0; j < 8; j++) {
            int gbase = h * HD + nv + (j >> 1) * 16;
            int p0 = pb + (j & 1);
            float* d0 = out + (size_t)rg0 * DM + gbase;
            float* d1 = out + (size_t)(rg0 + 8) * DM + gbase;
            d0[p0]     = ftf32(o[mi][j][0] * inv0);
            d0[p0 + 4] = ftf32(o[mi][j][1] * inv0);
            d1[p0]     = ftf32(o[mi][j][2] * inv1);
            d1[p0 + 4] = ftf32(o[mi][j][3] * inv1);
        }
    }
}

// ===========================================================================
// Host side
// ===========================================================================
extern "C" void kernel_launch(void* const* d_in, const int* in_sizes, int n_in,
                              void* d_out, int out_size)
{
    const float* x     = (const float*)d_in[0];
    const float* w_qkv = (const float*)d_in[2];
    const float* w_out = (const float*)d_in[3];
    float* out = (float*)d_out;

    float *qkv, *attn, *xp, *wqkvp, *woutp;
    cudaGetSymbolAddress((void**)&qkv,   g_qkv);
    cudaGetSymbolAddress((void**)&attn,  g_attn);
    cudaGetSymbolAddress((void**)&xp,    g_xp);
    cudaGetSymbolAddress((void**)&wqkvp, g_wqkvp);
    cudaGetSymbolAddress((void**)&woutp, g_woutp);

    cudaFuncSetAttribute(gemm_mma, cudaFuncAttributeMaxDynamicSharedMemorySize,
                         GEMM_SMEM_BYTES);
    cudaFuncSetAttribute(attn_mma_kernel, cudaFuncAttributeMaxDynamicSharedMemorySize,
                         ATT_SMEM);

    // 0) inv_freq table + permute/round GEMM operands (16-group permutation)
    init_invf_kernel<<<1, 64>>>();
    {
        int n16x = TT * DM / 16;
        perm_round_kernel<<<(n16x + 255) / 256, 256>>>((const float4*)x, (float4*)xp, n16x);
        int n16q = QKV_N * DM / 16;
        perm_round_kernel<<<(n16q + 255) / 256, 256>>>((const float4*)w_qkv, (float4*)wqkvp, n16q);
        int n16o = DM * DM / 16;
        perm_round_kernel<<<(n16o + 255) / 256, 256>>>((const float4*)w_out, (float4*)woutp, n16o);
    }

    // 1) QKV projection + fused RoPE/clamp epilogue
    {
        dim3 grid(QKV_N / 128, TT / 128);
        gemm_mma<<<grid, 256, GEMM_SMEM_BYTES>>>(xp, wqkvp, qkv, QKV_N, DM, 1);
    }

    // 2) Tensor-core flash attention (writes 16-group permuted + rounded)
    {
        dim3 grid(TT / 128, NH);
        attn_mma_kernel<<<grid, 256, ATT_SMEM>>>(attn);
    }

    // 3) Output projection
    {
        dim3 grid(DM / 128, TT / 128);
        gemm_mma<<<grid, 256, GEMM_SMEM_BYTES>>>(attn, woutp, out, DM, DM, 0);
    }
}

// round 14
// speedup vs baseline: 1.1310x; 1.1310x over previous
#include <cuda_runtime.h>
#include <cuda_bf16.h>
#include <math.h>
#include <stdint.h>

// Problem constants
#define TT      2048
#define DM      6144
#define NH      48
#define NKV     8
#define HD      128
#define QKV_N   8192
#define KV_OFF  DM
#define V_OFF   (DM + NKV*HD)
#define REP     (NH / NKV)
#define CLAMP_V 8.0f

// Scratch (static device globals)
__device__ float g_qkv[(size_t)TT * QKV_N];
__device__ float g_attn[(size_t)TT * DM];
__device__ float g_xp[(size_t)TT * DM];
__device__ float g_wqkvp[(size_t)QKV_N * DM];
__device__ float g_woutp[(size_t)DM * DM];
__device__ float g_invf[64];

// ===========================================================================
// Helpers
// ===========================================================================
__device__ __forceinline__ uint32_t smem_to_u32(const void* p) {
    uint32_t a;
    asm("{ .reg .u64 t; cvta.to.shared.u64 t, %1; cvt.u32.u64 %0, t; }"
        : "=r"(a) : "l"(p));
    return a;
}
__device__ __forceinline__ void cp16(uint32_t s, const void* g) {
    asm volatile("cp.async.cg.shared.global [%0], [%1], 16;"
                 :: "r"(s), "l"(g) : "memory");
}
__device__ __forceinline__ float ftf32(float x) {
    uint32_t o, i = __float_as_uint(x);
    asm("cvt.rna.tf32.f32 %0, %1;" : "=r"(o) : "r"(i));
    return __uint_as_float(o);
}
__device__ __forceinline__ void mma8(float* d, const uint32_t* a, const uint32_t* b) {
    asm volatile(
        "mma.sync.aligned.m16n8k8.row.col.f32.tf32.tf32.f32 "
        "{%0,%1,%2,%3}, {%4,%5,%6,%7}, {%8,%9}, {%0,%1,%2,%3};"
        : "+f"(d[0]), "+f"(d[1]), "+f"(d[2]), "+f"(d[3])
        : "r"(a[0]), "r"(a[1]), "r"(a[2]), "r"(a[3]), "r"(b[0]), "r"(b[1]));
}
__device__ __forceinline__ void mma16bf(float* d, const uint32_t* a, const uint32_t* b) {
    asm volatile(
        "mma.sync.aligned.m16n8k16.row.col.f32.bf16.bf16.f32 "
        "{%0,%1,%2,%3}, {%4,%5,%6,%7}, {%8,%9}, {%0,%1,%2,%3};"
        : "+f"(d[0]), "+f"(d[1]), "+f"(d[2]), "+f"(d[3])
        : "r"(a[0]), "r"(a[1]), "r"(a[2]), "r"(a[3]), "r"(b[0]), "r"(b[1]));
}
__device__ __forceinline__ uint32_t packsplit(float x, float y, uint32_t& lo) {
    __nv_bfloat16 hx = __float2bfloat16(x);
    __nv_bfloat16 hy = __float2bfloat16(y);
    float rx = x - __bfloat162float(hx);
    float ry = y - __bfloat162float(hy);
    __nv_bfloat16 lx = __float2bfloat16(rx);
    __nv_bfloat16 ly = __float2bfloat16(ry);
    lo = ((uint32_t)__bfloat16_as_ushort(ly) << 16) | __bfloat16_as_ushort(lx);
    return ((uint32_t)__bfloat16_as_ushort(hy) << 16) | __bfloat16_as_ushort(hx);
}
__device__ __forceinline__ float clmp(float v) {
    return fminf(fmaxf(v, -CLAMP_V), CLAMP_V);
}

// ===========================================================================
// inv_freq table
// ===========================================================================
__global__ void init_invf_kernel()
{
    int i = threadIdx.x;
    g_invf[i] = (float)pow(500000.0, -(double)i / 64.0);
}

// ===========================================================================
// Permute (within-8 interleave [0,4,1,5,2,6,3,7]) + rna-tf32 round.
// ===========================================================================
__global__ __launch_bounds__(256)
void perm_round_kernel(const float4* __restrict__ src, float4* __restrict__ dst, int n8)
{
    int g = blockIdx.x * blockDim.x + threadIdx.x;
    if (g < n8) {
        float4 i0 = src[2 * g];
        float4 i1 = src[2 * g + 1];
        float4 o0 = make_float4(ftf32(i0.x), ftf32(i1.x), ftf32(i0.y), ftf32(i1.y));
        float4 o1 = make_float4(ftf32(i0.z), ftf32(i1.z), ftf32(i0.w), ftf32(i1.w));
        dst[2 * g]     = o0;
        dst[2 * g + 1] = o1;
    }
}

// ===========================================================================
// tf32 mma.sync GEMM on K-PERMUTED (8-group) pre-rounded operands.
// R12 winner core. R14: 1D grid + M-band rasterization (band = 8 M-tiles x
// all N-tiles) for L2 reuse of the B (weight) matrix. Pure scheduling change.
// mode 1: fused RoPE+clamp epilogue.
// ===========================================================================
#define TSZ  (128 * 32)
#define GEMM_SMEM_BYTES (6 * TSZ * 4)
#define BAND 8

__global__ __launch_bounds__(256, 2)
void gemm_mma(const float* __restrict__ A, const float* __restrict__ B,
              float* __restrict__ C, int N, int K, int Mt, int mode)
{
    extern __shared__ float sm[];
    const int tid  = threadIdx.x;
    const int wid  = tid >> 5, lane = tid & 31;
    const int wm   = (wid >> 2) * 64;
    const int wn   = (wid & 3) * 32;
    const int gr   = lane >> 2, tc = lane & 3;

    // ---- M-band raster: bands of BAND M-tiles x all N-tiles ----
    const int Nt   = N / 128;
    const int bid  = blockIdx.x;
    const int band = bid / (BAND * Nt);
    const int rem  = bid - band * (BAND * Nt);
    const int by   = band * BAND + (rem % BAND);
    const int bx   = rem / BAND;
    const int bm   = by * 128, bn = bx * 128;
    (void)Mt;

    const int ldr = tid >> 3;
    const int ldu = tid & 7;

    const uint32_t sbase = smem_to_u32(sm);
    const int NS = K / 32;

    float acc[4][4][4];
#pragma unroll
    for (int i = 0; i < 4; i++)
#pragma unroll
        for (int j = 0; j < 4; j++)
#pragma unroll
            for (int r = 0; r < 4; r++) acc[i][j][r] = 0.f;

    const int lsw = (ldr & 3) << 1;
    const int lu  = (ldu ^ lsw) << 2;

    auto loadTiles = [&](int k0, int st) {
#pragma unroll
        for (int v = 0; v < 4; v++) {
            int row = ldr + v * 32;
            uint32_t sa = sbase + (uint32_t)(st * TSZ + row * 32 + lu) * 4;
            cp16(sa, A + (size_t)(bm + row) * K + k0 + ldu * 4);
            uint32_t sb = sbase + (uint32_t)(3 * TSZ + st * TSZ + row * 32 + lu) * 4;
            cp16(sb, B + (size_t)(bn + row) * K + k0 + ldu * 4);
        }
        asm volatile("cp.async.commit_group;" ::: "memory");
    };

    loadTiles(0, 0);
    loadTiles(32, 1);

    const int asw = (gr & 3) << 1;
    const int ain = 2 * (tc & 1);
    int uofs[4];
#pragma unroll
    for (int ks = 0; ks < 4; ks++) {
        int u = 2 * ks + (tc >> 1);
        uofs[ks] = ((u ^ asw) << 2) + ain;
    }
    int arow[4], brow[4];
#pragma unroll
    for (int i = 0; i < 4; i++) arow[i] = (wm + i * 16 + gr) * 32;
#pragma unroll
    for (int j = 0; j < 4; j++) brow[j] = (wn + j * 8 + gr) * 32;

    int st = 0;
    for (int s = 0; s < NS; s++) {
        asm volatile("cp.async.wait_group 1;" ::: "memory");
        __syncthreads();

        int nst = st + 2; if (nst >= 3) nst -= 3;
        if (s + 2 < NS) loadTiles((s + 2) * 32, nst);
        else asm volatile("cp.async.commit_group;" ::: "memory");

        const float* As_ = sm + st * TSZ;
        const float* Bs_ = sm + 3 * TSZ + st * TSZ;

        uint32_t afr[2][4][4], bfr[2][4][2];
        auto loadFrags = [&](int ks, uint32_t af[4][4], uint32_t bf[4][2]) {
            const int uof = uofs[ks];
#pragma unroll
            for (int i = 0; i < 4; i++) {
                const float* ap = As_ + arow[i] + uof;
                float2 alo = *(const float2*)(ap);
                float2 ahi = *(const float2*)(ap + 256);
                af[i][0] = __float_as_uint(alo.x);
                af[i][1] = __float_as_uint(ahi.x);
                af[i][2] = __float_as_uint(alo.y);
                af[i][3] = __float_as_uint(ahi.y);
            }
#pragma unroll
            for (int j = 0; j < 4; j++) {
                float2 bv = *(const float2*)(Bs_ + brow[j] + uof);
                bf[j][0] = __float_as_uint(bv.x);
                bf[j][1] = __float_as_uint(bv.y);
            }
        };

        loadFrags(0, afr[0], bfr[0]);
#pragma unroll
        for (int ks = 0; ks < 4; ks++) {
            if (ks < 3) loadFrags(ks + 1, afr[(ks + 1) & 1], bfr[(ks + 1) & 1]);
            uint32_t (*a)[4] = afr[ks & 1];
            uint32_t (*b)[2] = bfr[ks & 1];
#pragma unroll
            for (int i = 0; i < 4; i++)
#pragma unroll
                for (int j = 0; j < 4; j++)
                    mma8(acc[i][j], a[i], b[j]);
        }

        if (++st == 3) st = 0;
    }

#pragma unroll
    for (int i = 0; i < 4; i++) {
#pragma unroll
        for (int j = 0; j < 4; j++) {
            int r = bm + wm + i * 16 + gr;
            int c = bn + wn + j * 8 + tc * 2;
            float2 v0 = make_float2(acc[i][j][0], acc[i][j][1]);
            float2 v1 = make_float2(acc[i][j][2], acc[i][j][3]);
            if (mode == 1) {
                if (c < V_OFF) {
                    int i64 = (c >> 1) & 63;
                    float inv = g_invf[i64];
                    float s0, c0;
                    sincosf((float)r * inv, &s0, &c0);
                    float a0 = v0.x, b0 = v0.y;
                    v0.x = clmp(a0 * c0 - b0 * s0);
                    v0.y = clmp(a0 * s0 + b0 * c0);
                    float s1, c1;
                    sincosf((float)(r + 8) * inv, &s1, &c1);
                    float a1 = v1.x, b1 = v1.y;
                    v1.x = clmp(a1 * c1 - b1 * s1);
                    v1.y = clmp(a1 * s1 + b1 * c1);
                } else {
                    v0.x = clmp(v0.x); v0.y = clmp(v0.y);
                    v1.x = clmp(v1.x); v1.y = clmp(v1.y);
                }
            }
            *(float2*)&C[(size_t)r * N + c]       = v0;
            *(float2*)&C[(size_t)(r + 8) * N + c] = v1;
        }
    }
}

// ===========================================================================
// Tensor-core flash attention (R12 winner, unchanged).
// ===========================================================================
#define A_QH   0
#define A_QL   34816
#define A_KH   69632
#define A_KL   87040
#define A_VTH  104448
#define A_VTL  122880
#define A_SS   141312
#define A_PHB  176128
#define A_PLB  194560
#define A_VS   176128
#define A_STAT 212992
#define ATT_SMEM 215552

__global__ __launch_bounds__(256, 1)
void attn_mma_kernel(float* __restrict__ out)
{
    extern __shared__ char smem[];
    uint32_t* QHw = (uint32_t*)(smem + A_QH);
    uint32_t* QLw = (uint32_t*)(smem + A_QL);
    uint32_t* KHw = (uint32_t*)(smem + A_KH);
    uint32_t* KLw = (uint32_t*)(smem + A_KL);
    uint32_t* VTH = (uint32_t*)(smem + A_VTH);
    uint32_t* VTL = (uint32_t*)(smem + A_VTL);
    float*    SS  = (float*)(smem + A_SS);
    uint32_t* PHB = (uint32_t*)(smem + A_PHB);
    uint32_t* PLB = (uint32_t*)(smem + A_PLB);
    float*    VS  = (float*)(smem + A_VS);
    float* rowM = (float*)(smem + A_STAT);
    float* rowL = rowM + 128;
    float* rowA = rowL + 128;
    float* PPAR = rowA + 128;

    const int qb   = gridDim.x - 1 - blockIdx.x;
    const int h    = blockIdx.y;
    const int kh   = h / REP;
    const int tid  = threadIdx.x;
    const int wid  = tid >> 5, lane = tid & 31;
    const int gr   = lane >> 2, tc = lane & 3;
    const int m0   = (wid >> 1) * 32;
    const int wn   = (wid & 1) * 32;
    const int nv   = (wid & 1) * 64;
    const float scale = 0.088388347648318447f;

    {
        const float* qg = g_qkv + (size_t)(qb * 128) * QKV_N + h * HD;
#pragma unroll
        for (int i = 0; i < 16; i++) {
            int f = tid + i * 256;
            int r = f >> 5;
            int c = (f & 31) * 4;
            float4 v = *(const float4*)(qg + (size_t)r * QKV_N + c);
            uint32_t l0, l1;
            uint32_t h0 = packsplit(v.x, v.y, l0);
            uint32_t h1 = packsplit(v.z, v.w, l1);
            QHw[r * 68 + c / 2]     = h0;
            QHw[r * 68 + c / 2 + 1] = h1;
            QLw[r * 68 + c / 2]     = l0;
            QLw[r * 68 + c / 2 + 1] = l1;
        }
    }
    if (tid < 128) { rowM[tid] = -1e30f; rowL[tid] = 0.f; }

    float o[2][8][4];
#pragma unroll
    for (int mi = 0; mi < 2; mi++)
#pragma unroll
        for (int j = 0; j < 8; j++)
#pragma unroll
            for (int r = 0; r < 4; r++) o[mi][j][r] = 0.f;

    const int nkt = 2 * qb + 2;
    for (int kt = 0; kt < nkt; kt++) {
        __syncthreads();

        {
            const float* kg = g_qkv + (size_t)(kt * 64) * QKV_N + KV_OFF + kh * HD;
            const float* vg = g_qkv + (size_t)(kt * 64) * QKV_N + V_OFF  + kh * HD;
#pragma unroll
            for (int i = 0; i < 8; i++) {
                int f = tid + i * 256;
                int r = f >> 5;
                int c = (f & 31) * 4;
                float4 kv = *(const float4*)(kg + (size_t)r * QKV_N + c);
                uint32_t l0, l1;
                uint32_t h0 = packsplit(kv.x, kv.y, l0);
                uint32_t h1 = packsplit(kv.z, kv.w, l1);
                KHw[r * 68 + c / 2]     = h0;
                KHw[r * 68 + c / 2 + 1] = h1;
                KLw[r * 68 + c / 2]     = l0;
                KLw[r * 68 + c / 2 + 1] = l1;
                float4 vv = *(const float4*)(vg + (size_t)r * QKV_N + c);
                VS[r * 133 + c + 0] = vv.x;
                VS[r * 133 + c + 1] = vv.y;
                VS[r * 133 + c + 2] = vv.z;
                VS[r * 133 + c + 3] = vv.w;
            }
        }
        __syncthreads();

#pragma unroll
        for (int i = 0; i < 16; i++) {
            int idx = tid + i * 256;
            int d = idx >> 5;
            int w = idx & 31;
            float v0 = VS[(2 * w) * 133 + d];
            float v1 = VS[(2 * w + 1) * 133 + d];
            uint32_t lo;
            uint32_t hi = packsplit(v0, v1, lo);
            VTH[d * 36 + w] = hi;
            VTL[d * 36 + w] = lo;
        }

        float sacc[2][4][4];
#pragma unroll
        for (int mi = 0; mi < 2; mi++)
#pragma unroll
            for (int j = 0; j < 4; j++)
#pragma unroll
                for (int r = 0; r < 4; r++) sacc[mi][j][r] = 0.f;

#pragma unroll
        for (int ks = 0; ks < 8; ks++) {
            uint32_t ah[2][4], al[2][4];
#pragma unroll
            for (int mi = 0; mi < 2; mi++) {
                int base = (m0 + mi * 16 + gr) * 68 + ks * 8 + tc;
                ah[mi][0] = QHw[base];
                ah[mi][1] = QHw[base + 8 * 68];
                ah[mi][2] = QHw[base + 4];
                ah[mi][3] = QHw[base + 8 * 68 + 4];
                al[mi][0] = QLw[base];
                al[mi][1] = QLw[base + 8 * 68];
                al[mi][2] = QLw[base + 4];
                al[mi][3] = QLw[base + 8 * 68 + 4];
            }
            uint32_t bh[4][2], bl[4][2];
#pragma unroll
            for (int j = 0; j < 4; j++) {
                int base = (wn + j * 8 + gr) * 68 + ks * 8 + tc;
                bh[j][0] = KHw[base];
                bh[j][1] = KHw[base + 4];
                bl[j][0] = KLw[base];
                bl[j][1] = KLw[base + 4];
            }
#pragma unroll
            for (int mi = 0; mi < 2; mi++)
#pragma unroll
                for (int j = 0; j < 4; j++) {
                    mma16bf(sacc[mi][j], ah[mi], bh[j]);
                    mma16bf(sacc[mi][j], ah[mi], bl[j]);
                    mma16bf(sacc[mi][j], al[mi], bh[j]);
                }
        }

        const bool dg = (kt >= 2 * qb);
#pragma unroll
        for (int mi = 0; mi < 2; mi++) {
#pragma unroll
            for (int j = 0; j < 4; j++) {
                int rl0 = m0 + mi * 16 + gr;
                int cl  = wn + j * 8 + 2 * tc;
                float v0 = sacc[mi][j][0] * scale;
                float v1 = sacc[mi][j][1] * scale;
                float v2 = sacc[mi][j][2] * scale;
                float v3 = sacc[mi][j][3] * scale;
                if (dg) {
                    int rg0 = qb * 128 + rl0;
                    int cg  = kt * 64 + cl;
                    if (cg     > rg0)     v0 = -1e30f;
                    if (cg + 1 > rg0)     v1 = -1e30f;
                    if (cg     > rg0 + 8) v2 = -1e30f;
                    if (cg + 1 > rg0 + 8) v3 = -1e30f;
                }
                *(float2*)&SS[rl0 * 68 + cl]       = make_float2(v0, v1);
                *(float2*)&SS[(rl0 + 8) * 68 + cl] = make_float2(v2, v3);
            }
        }
        __syncthreads();

        {
            const int r  = tid & 127;
            const int hf = tid >> 7;
            const float4* srow = (const float4*)(SS + r * 68) + hf * 8;
            float4 sv[8];
            float pm = -1e30f;
#pragma unroll
            for (int jj = 0; jj < 8; jj++) {
                sv[jj] = srow[jj];
                pm = fmaxf(pm, fmaxf(fmaxf(sv[jj].x, sv[jj].y), fmaxf(sv[jj].z, sv[jj].w)));
            }
            PPAR[tid] = pm;
            __syncthreads();
            float mOld = rowM[r];
            float m = fmaxf(mOld, fmaxf(PPAR[r], PPAR[r + 128]));
            float l = 0.f;
            uint32_t* phh = PHB + r * 36 + hf * 16;
            uint32_t* pll = PLB + r * 36 + hf * 16;
#pragma unroll
            for (int jj = 0; jj < 8; jj++) {
                float p0 = __expf(sv[jj].x - m);
                float p1 = __expf(sv[jj].y - m);
                float p2 = __expf(sv[jj].z - m);
                float p3 = __expf(sv[jj].w - m);
                l += (p0 + p1) + (p2 + p3);
                uint32_t lo0, lo1;
                uint32_t h0 = packsplit(p0, p1, lo0);
                uint32_t h1 = packsplit(p2, p3, lo1);
                phh[2 * jj]     = h0;
                phh[2 * jj + 1] = h1;
                pll[2 * jj]     = lo0;
                pll[2 * jj + 1] = lo1;
            }
            PPAR[tid] = l;
            __syncthreads();
            if (tid < 128) {
                float alpha = __expf(mOld - m);
                rowL[r] = rowL[r] * alpha + (PPAR[r] + PPAR[r + 128]);
                rowM[r] = m;
                rowA[r] = alpha;
            }
        }
        __syncthreads();

#pragma unroll
        for (int mi = 0; mi < 2; mi++) {
            float am0 = rowA[m0 + mi * 16 + gr];
            float am1 = rowA[m0 + mi * 16 + gr + 8];
#pragma unroll
            for (int j = 0; j < 8; j++) {
                o[mi][j][0] *= am0; o[mi][j][1] *= am0;
                o[mi][j][2] *= am1; o[mi][j][3] *= am1;
            }
        }
#pragma unroll
        for (int ks = 0; ks < 4; ks++) {
            uint32_t aph[2][4], apl[2][4];
#pragma unroll
            for (int mi = 0; mi < 2; mi++) {
                int base = (m0 + mi * 16 + gr) * 36 + ks * 8 + tc;
                aph[mi][0] = PHB[base];
                aph[mi][1] = PHB[base + 8 * 36];
                aph[mi][2] = PHB[base + 4];
                aph[mi][3] = PHB[base + 8 * 36 + 4];
                apl[mi][0] = PLB[base];
                apl[mi][1] = PLB[base + 8 * 36];
                apl[mi][2] = PLB[base + 4];
                apl[mi][3] = PLB[base + 8 * 36 + 4];
            }
#pragma unroll
            for (int j = 0; j < 8; j++) {
                int base = (nv + j * 8 + gr) * 36 + ks * 8 + tc;
                uint32_t bh[2], bl[2];
                bh[0] = VTH[base];
                bh[1] = VTH[base + 4];
                bl[0] = VTL[base];
                bl[1] = VTL[base + 4];
#pragma unroll
                for (int mi = 0; mi < 2; mi++) {
                    mma16bf(o[mi][j], aph[mi], bh);
                    mma16bf(o[mi][j], aph[mi], bl);
                    mma16bf(o[mi][j], apl[mi], bh);
                }
            }
        }
    }

    // normalize + rna-round + K-PERMUTED (8-group) store
    const int p0 = (tc < 2) ? 4 * tc     : 4 * tc - 7;
    const int p1 = (tc < 2) ? 4 * tc + 2 : 4 * tc - 5;
#pragma unroll
    for (int mi = 0; mi < 2; mi++) {
        int rl0 = m0 + mi * 16 + gr;
        float inv0 = 1.f / rowL[rl0];
        float inv1 = 1.f / rowL[rl0 + 8];
        int rg0 = qb * 128 + rl0;
#pragma unroll
        for (int j = 0; j < 8; j++) {
            int gbase = h * HD + nv + j * 8;
            float* d0 = out + (size_t)rg0 * DM + gbase;
            float* d1 = out + (size_t)(rg0 + 8) * DM + gbase;
            d0[p0] = ftf32(o[mi][j][0] * inv0);
            d0[p1] = ftf32(o[mi][j][1] * inv0);
            d1[p0] = ftf32(o[mi][j][2] * inv1);
            d1[p1] = ftf32(o[mi][j][3] * inv1);
        }
    }
}

// ===========================================================================
// Host side
// ===========================================================================
extern "C" void kernel_launch(void* const* d_in, const int* in_sizes, int n_in,
                              void* d_out, int out_size)
{
    const float* x     = (const float*)d_in[0];
    const float* w_qkv = (const float*)d_in[2];
    const float* w_out = (const float*)d_in[3];
    float* out = (float*)d_out;

    float *qkv, *attn, *xp, *wqkvp, *woutp;
    cudaGetSymbolAddress((void**)&qkv,   g_qkv);
    cudaGetSymbolAddress((void**)&attn,  g_attn);
    cudaGetSymbolAddress((void**)&xp,    g_xp);
    cudaGetSymbolAddress((void**)&wqkvp, g_wqkvp);
    cudaGetSymbolAddress((void**)&woutp, g_woutp);

    cudaFuncSetAttribute(gemm_mma, cudaFuncAttributeMaxDynamicSharedMemorySize,
                         GEMM_SMEM_BYTES);
    cudaFuncSetAttribute(attn_mma_kernel, cudaFuncAttributeMaxDynamicSharedMemorySize,
                         ATT_SMEM);

    // 0) inv_freq table + permute/round GEMM operands (8-group permutation)
    init_invf_kernel<<<1, 64>>>();
    {
        int n8x = TT * DM / 8;
        perm_round_kernel<<<(n8x + 255) / 256, 256>>>((const float4*)x, (float4*)xp, n8x);
        int n8q = QKV_N * DM / 8;
        perm_round_kernel<<<(n8q + 255) / 256, 256>>>((const float4*)w_qkv, (float4*)wqkvp, n8q);
        int n8o = DM * DM / 8;
        perm_round_kernel<<<(n8o + 255) / 256, 256>>>((const float4*)w_out, (float4*)woutp, n8o);
    }

    // 1) QKV projection + fused RoPE/clamp epilogue  (M-band raster grid)
    {
        int Mt = TT / 128, Nt = QKV_N / 128;
        gemm_mma<<<Mt * Nt, 256, GEMM_SMEM_BYTES>>>(xp, wqkvp, qkv, QKV_N, DM, Mt, 1);
    }

    // 2) Tensor-core flash attention (writes 8-group permuted + rounded)
    {
        dim3 grid(TT / 128, NH);
        attn_mma_kernel<<<grid, 256, ATT_SMEM>>>(attn);
    }

    // 3) Output projection  (M-band raster grid)
    {
        int Mt = TT / 128, Nt = DM / 128;
        gemm_mma<<<Mt * Nt, 256, GEMM_SMEM_BYTES>>>(attn, woutp, out, DM, DM, Mt, 0);
    }
}

// round 15
// speedup vs baseline: 1.1608x; 1.0264x over previous
#include <cuda_runtime.h>
#include <cuda_bf16.h>
#include <math.h>
#include <stdint.h>

// Problem constants
#define TT      2048
#define DM      6144
#define NH      48
#define NKV     8
#define HD      128
#define QKV_N   8192
#define KV_OFF  DM
#define V_OFF   (DM + NKV*HD)
#define REP     (NH / NKV)
#define CLAMP_V 8.0f

// Scratch (static device globals)
__device__ float g_qkv[(size_t)TT * QKV_N];
__device__ float g_attn[(size_t)TT * DM];
__device__ float g_xp[(size_t)TT * DM];
__device__ float g_wqkvp[(size_t)QKV_N * DM];
__device__ float g_woutp[(size_t)DM * DM];
__device__ float g_invf[64];

// ===========================================================================
// Helpers
// ===========================================================================
__device__ __forceinline__ uint32_t smem_to_u32(const void* p) {
    uint32_t a;
    asm("{ .reg .u64 t; cvta.to.shared.u64 t, %1; cvt.u32.u64 %0, t; }"
        : "=r"(a) : "l"(p));
    return a;
}
__device__ __forceinline__ void cp16(uint32_t s, const void* g) {
    asm volatile("cp.async.cg.shared.global [%0], [%1], 16;"
                 :: "r"(s), "l"(g) : "memory");
}
__device__ __forceinline__ float ftf32(float x) {
    uint32_t o, i = __float_as_uint(x);
    asm("cvt.rna.tf32.f32 %0, %1;" : "=r"(o) : "r"(i));
    return __uint_as_float(o);
}
__device__ __forceinline__ void mma8(float* d, const uint32_t* a, const uint32_t* b) {
    asm volatile(
        "mma.sync.aligned.m16n8k8.row.col.f32.tf32.tf32.f32 "
        "{%0,%1,%2,%3}, {%4,%5,%6,%7}, {%8,%9}, {%0,%1,%2,%3};"
        : "+f"(d[0]), "+f"(d[1]), "+f"(d[2]), "+f"(d[3])
        : "r"(a[0]), "r"(a[1]), "r"(a[2]), "r"(a[3]), "r"(b[0]), "r"(b[1]));
}
__device__ __forceinline__ void mma16bf(float* d, const uint32_t* a, const uint32_t* b) {
    asm volatile(
        "mma.sync.aligned.m16n8k16.row.col.f32.bf16.bf16.f32 "
        "{%0,%1,%2,%3}, {%4,%5,%6,%7}, {%8,%9}, {%0,%1,%2,%3};"
        : "+f"(d[0]), "+f"(d[1]), "+f"(d[2]), "+f"(d[3])
        : "r"(a[0]), "r"(a[1]), "r"(a[2]), "r"(a[3]), "r"(b[0]), "r"(b[1]));
}
__device__ __forceinline__ uint32_t packsplit(float x, float y, uint32_t& lo) {
    __nv_bfloat16 hx = __float2bfloat16(x);
    __nv_bfloat16 hy = __float2bfloat16(y);
    float rx = x - __bfloat162float(hx);
    float ry = y - __bfloat162float(hy);
    __nv_bfloat16 lx = __float2bfloat16(rx);
    __nv_bfloat16 ly = __float2bfloat16(ry);
    lo = ((uint32_t)__bfloat16_as_ushort(ly) << 16) | __bfloat16_as_ushort(lx);
    return ((uint32_t)__bfloat16_as_ushort(hy) << 16) | __bfloat16_as_ushort(hx);
}
__device__ __forceinline__ float clmp(float v) {
    return fminf(fmaxf(v, -CLAMP_V), CLAMP_V);
}

// ===========================================================================
// inv_freq table
// ===========================================================================
__global__ void init_invf_kernel()
{
    int i = threadIdx.x;
    g_invf[i] = (float)pow(500000.0, -(double)i / 64.0);
}

// ===========================================================================
// Permute (within-8 interleave [0,4,1,5,2,6,3,7]) + rna-tf32 round.
// ===========================================================================
__global__ __launch_bounds__(256)
void perm_round_kernel(const float4* __restrict__ src, float4* __restrict__ dst, int n8)
{
    int g = blockIdx.x * blockDim.x + threadIdx.x;
    if (g < n8) {
        float4 i0 = src[2 * g];
        float4 i1 = src[2 * g + 1];
        float4 o0 = make_float4(ftf32(i0.x), ftf32(i1.x), ftf32(i0.y), ftf32(i1.y));
        float4 o1 = make_float4(ftf32(i0.z), ftf32(i1.z), ftf32(i0.w), ftf32(i1.w));
        dst[2 * g]     = o0;
        dst[2 * g + 1] = o1;
    }
}

// ===========================================================================
// tf32 mma.sync GEMM (R12 winner, 2D grid restored).
// ===========================================================================
#define TSZ  (128 * 32)
#define GEMM_SMEM_BYTES (6 * TSZ * 4)

__global__ __launch_bounds__(256, 2)
void gemm_mma(const float* __restrict__ A, const float* __restrict__ B,
              float* __restrict__ C, int N, int K, int mode)
{
    extern __shared__ float sm[];
    const int tid  = threadIdx.x;
    const int wid  = tid >> 5, lane = tid & 31;
    const int wm   = (wid >> 2) * 64;
    const int wn   = (wid & 3) * 32;
    const int gr   = lane >> 2, tc = lane & 3;
    const int bm   = blockIdx.y * 128, bn = blockIdx.x * 128;

    const int ldr = tid >> 3;
    const int ldu = tid & 7;

    const uint32_t sbase = smem_to_u32(sm);
    const int NS = K / 32;

    float acc[4][4][4];
#pragma unroll
    for (int i = 0; i < 4; i++)
#pragma unroll
        for (int j = 0; j < 4; j++)
#pragma unroll
            for (int r = 0; r < 4; r++) acc[i][j][r] = 0.f;

    const int lsw = (ldr & 3) << 1;
    const int lu  = (ldu ^ lsw) << 2;

    auto loadTiles = [&](int k0, int st) {
#pragma unroll
        for (int v = 0; v < 4; v++) {
            int row = ldr + v * 32;
            uint32_t sa = sbase + (uint32_t)(st * TSZ + row * 32 + lu) * 4;
            cp16(sa, A + (size_t)(bm + row) * K + k0 + ldu * 4);
            uint32_t sb = sbase + (uint32_t)(3 * TSZ + st * TSZ + row * 32 + lu) * 4;
            cp16(sb, B + (size_t)(bn + row) * K + k0 + ldu * 4);
        }
        asm volatile("cp.async.commit_group;" ::: "memory");
    };

    loadTiles(0, 0);
    loadTiles(32, 1);

    const int asw = (gr & 3) << 1;
    const int ain = 2 * (tc & 1);
    int uofs[4];
#pragma unroll
    for (int ks = 0; ks < 4; ks++) {
        int u = 2 * ks + (tc >> 1);
        uofs[ks] = ((u ^ asw) << 2) + ain;
    }
    int arow[4], brow[4];
#pragma unroll
    for (int i = 0; i < 4; i++) arow[i] = (wm + i * 16 + gr) * 32;
#pragma unroll
    for (int j = 0; j < 4; j++) brow[j] = (wn + j * 8 + gr) * 32;

    int st = 0;
    for (int s = 0; s < NS; s++) {
        asm volatile("cp.async.wait_group 1;" ::: "memory");
        __syncthreads();

        int nst = st + 2; if (nst >= 3) nst -= 3;
        if (s + 2 < NS) loadTiles((s + 2) * 32, nst);
        else asm volatile("cp.async.commit_group;" ::: "memory");

        const float* As_ = sm + st * TSZ;
        const float* Bs_ = sm + 3 * TSZ + st * TSZ;

        uint32_t afr[2][4][4], bfr[2][4][2];
        auto loadFrags = [&](int ks, uint32_t af[4][4], uint32_t bf[4][2]) {
            const int uof = uofs[ks];
#pragma unroll
            for (int i = 0; i < 4; i++) {
                const float* ap = As_ + arow[i] + uof;
                float2 alo = *(const float2*)(ap);
                float2 ahi = *(const float2*)(ap + 256);
                af[i][0] = __float_as_uint(alo.x);
                af[i][1] = __float_as_uint(ahi.x);
                af[i][2] = __float_as_uint(alo.y);
                af[i][3] = __float_as_uint(ahi.y);
            }
#pragma unroll
            for (int j = 0; j < 4; j++) {
                float2 bv = *(const float2*)(Bs_ + brow[j] + uof);
                bf[j][0] = __float_as_uint(bv.x);
                bf[j][1] = __float_as_uint(bv.y);
            }
        };

        loadFrags(0, afr[0], bfr[0]);
#pragma unroll
        for (int ks = 0; ks < 4; ks++) {
            if (ks < 3) loadFrags(ks + 1, afr[(ks + 1) & 1], bfr[(ks + 1) & 1]);
            uint32_t (*a)[4] = afr[ks & 1];
            uint32_t (*b)[2] = bfr[ks & 1];
#pragma unroll
            for (int i = 0; i < 4; i++)
#pragma unroll
                for (int j = 0; j < 4; j++)
                    mma8(acc[i][j], a[i], b[j]);
        }

        if (++st == 3) st = 0;
    }

#pragma unroll
    for (int i = 0; i < 4; i++) {
#pragma unroll
        for (int j = 0; j < 4; j++) {
            int r = bm + wm + i * 16 + gr;
            int c = bn + wn + j * 8 + tc * 2;
            float2 v0 = make_float2(acc[i][j][0], acc[i][j][1]);
            float2 v1 = make_float2(acc[i][j][2], acc[i][j][3]);
            if (mode == 1) {
                if (c < V_OFF) {
                    int i64 = (c >> 1) & 63;
                    float inv = g_invf[i64];
                    float s0, c0;
                    sincosf((float)r * inv, &s0, &c0);
                    float a0 = v0.x, b0 = v0.y;
                    v0.x = clmp(a0 * c0 - b0 * s0);
                    v0.y = clmp(a0 * s0 + b0 * c0);
                    float s1, c1;
                    sincosf((float)(r + 8) * inv, &s1, &c1);
                    float a1 = v1.x, b1 = v1.y;
                    v1.x = clmp(a1 * c1 - b1 * s1);
                    v1.y = clmp(a1 * s1 + b1 * c1);
                } else {
                    v0.x = clmp(v0.x); v0.y = clmp(v0.y);
                    v1.x = clmp(v1.x); v1.y = clmp(v1.y);
                }
            }
            *(float2*)&C[(size_t)r * N + c]       = v0;
            *(float2*)&C[(size_t)(r + 8) * N + c] = v1;
        }
    }
}

// ===========================================================================
// Tensor-core flash attention (R12 core).
// R15: K/V global loads software-pipelined through registers -- LDGs for
// tile kt+1 are issued right after the STS of tile kt, so their latency
// overlaps the whole tile's compute. Numerics bit-identical to R12.
// ===========================================================================
#define A_QH   0
#define A_QL   34816
#define A_KH   69632
#define A_KL   87040
#define A_VTH  104448
#define A_VTL  122880
#define A_SS   141312
#define A_PHB  176128
#define A_PLB  194560
#define A_VS   176128
#define A_STAT 212992
#define ATT_SMEM 215552

__global__ __launch_bounds__(256, 1)
void attn_mma_kernel(float* __restrict__ out)
{
    extern __shared__ char smem[];
    uint32_t* QHw = (uint32_t*)(smem + A_QH);
    uint32_t* QLw = (uint32_t*)(smem + A_QL);
    uint32_t* KHw = (uint32_t*)(smem + A_KH);
    uint32_t* KLw = (uint32_t*)(smem + A_KL);
    uint32_t* VTH = (uint32_t*)(smem + A_VTH);
    uint32_t* VTL = (uint32_t*)(smem + A_VTL);
    float*    SS  = (float*)(smem + A_SS);
    uint32_t* PHB = (uint32_t*)(smem + A_PHB);
    uint32_t* PLB = (uint32_t*)(smem + A_PLB);
    float*    VS  = (float*)(smem + A_VS);
    float* rowM = (float*)(smem + A_STAT);
    float* rowL = rowM + 128;
    float* rowA = rowL + 128;
    float* PPAR = rowA + 128;

    const int qb   = gridDim.x - 1 - blockIdx.x;
    const int h    = blockIdx.y;
    const int kh   = h / REP;
    const int tid  = threadIdx.x;
    const int wid  = tid >> 5, lane = tid & 31;
    const int gr   = lane >> 2, tc = lane & 3;
    const int m0   = (wid >> 1) * 32;
    const int wn   = (wid & 1) * 32;
    const int nv   = (wid & 1) * 64;
    const float scale = 0.088388347648318447f;

    // per-thread KV load coordinates (fixed across tiles)
    const int lrow[8] = {
        (tid + 0 * 256) >> 5, (tid + 1 * 256) >> 5, (tid + 2 * 256) >> 5,
        (tid + 3 * 256) >> 5, (tid + 4 * 256) >> 5, (tid + 5 * 256) >> 5,
        (tid + 6 * 256) >> 5, (tid + 7 * 256) >> 5 };
    const int lcol = (tid & 31) * 4;

    {
        const float* qg = g_qkv + (size_t)(qb * 128) * QKV_N + h * HD;
#pragma unroll
        for (int i = 0; i < 16; i++) {
            int f = tid + i * 256;
            int r = f >> 5;
            int c = (f & 31) * 4;
            float4 v = *(const float4*)(qg + (size_t)r * QKV_N + c);
            uint32_t l0, l1;
            uint32_t h0 = packsplit(v.x, v.y, l0);
            uint32_t h1 = packsplit(v.z, v.w, l1);
            QHw[r * 68 + c / 2]     = h0;
            QHw[r * 68 + c / 2 + 1] = h1;
            QLw[r * 68 + c / 2]     = l0;
            QLw[r * 68 + c / 2 + 1] = l1;
        }
    }
    if (tid < 128) { rowM[tid] = -1e30f; rowL[tid] = 0.f; }

    float o[2][8][4];
#pragma unroll
    for (int mi = 0; mi < 2; mi++)
#pragma unroll
        for (int j = 0; j < 8; j++)
#pragma unroll
            for (int r = 0; r < 4; r++) o[mi][j][r] = 0.f;

    // staged K/V registers + prefetch of tile 0
    float4 kreg[8], vreg[8];
    auto ldkv = [&](int kt) {
        const float* kg = g_qkv + (size_t)(kt * 64) * QKV_N + KV_OFF + kh * HD;
        const float* vg = g_qkv + (size_t)(kt * 64) * QKV_N + V_OFF  + kh * HD;
#pragma unroll
        for (int i = 0; i < 8; i++) {
            kreg[i] = *(const float4*)(kg + (size_t)lrow[i] * QKV_N + lcol);
            vreg[i] = *(const float4*)(vg + (size_t)lrow[i] * QKV_N + lcol);
        }
    };
    ldkv(0);

    const int nkt = 2 * qb + 2;
    for (int kt = 0; kt < nkt; kt++) {
        __syncthreads();   // prev PV done before clobbering K / VS(=PHB/PLB)

        // ---- STS staged K (split) + V (stage) from registers ----
#pragma unroll
        for (int i = 0; i < 8; i++) {
            int r = lrow[i];
            int c = lcol;
            uint32_t l0, l1;
            uint32_t h0 = packsplit(kreg[i].x, kreg[i].y, l0);
            uint32_t h1 = packsplit(kreg[i].z, kreg[i].w, l1);
            KHw[r * 68 + c / 2]     = h0;
            KHw[r * 68 + c / 2 + 1] = h1;
            KLw[r * 68 + c / 2]     = l0;
            KLw[r * 68 + c / 2 + 1] = l1;
            VS[r * 133 + c + 0] = vreg[i].x;
            VS[r * 133 + c + 1] = vreg[i].y;
            VS[r * 133 + c + 2] = vreg[i].z;
            VS[r * 133 + c + 3] = vreg[i].w;
        }
        // ---- prefetch next tile (latency overlaps this tile's compute) ----
        if (kt + 1 < nkt) ldkv(kt + 1);
        __syncthreads();

        // ---- Transpose V + bf16 split ----
#pragma unroll
        for (int i = 0; i < 16; i++) {
            int idx = tid + i * 256;
            int d = idx >> 5;
            int w = idx & 31;
            float v0 = VS[(2 * w) * 133 + d];
            float v1 = VS[(2 * w + 1) * 133 + d];
            uint32_t lo;
            uint32_t hi = packsplit(v0, v1, lo);
            VTH[d * 36 + w] = hi;
            VTL[d * 36 + w] = lo;
        }

        // ---- S = Q K^T (bf16x3) ----
        float sacc[2][4][4];
#pragma unroll
        for (int mi = 0; mi < 2; mi++)
#pragma unroll
            for (int j = 0; j < 4; j++)
#pragma unroll
                for (int r = 0; r < 4; r++) sacc[mi][j][r] = 0.f;

#pragma unroll
        for (int ks = 0; ks < 8; ks++) {
            uint32_t ah[2][4], al[2][4];
#pragma unroll
            for (int mi = 0; mi < 2; mi++) {
                int base = (m0 + mi * 16 + gr) * 68 + ks * 8 + tc;
                ah[mi][0] = QHw[base];
                ah[mi][1] = QHw[base + 8 * 68];
                ah[mi][2] = QHw[base + 4];
                ah[mi][3] = QHw[base + 8 * 68 + 4];
                al[mi][0] = QLw[base];
                al[mi][1] = QLw[base + 8 * 68];
                al[mi][2] = QLw[base + 4];
                al[mi][3] = QLw[base + 8 * 68 + 4];
            }
            uint32_t bh[4][2], bl[4][2];
#pragma unroll
            for (int j = 0; j < 4; j++) {
                int base = (wn + j * 8 + gr) * 68 + ks * 8 + tc;
                bh[j][0] = KHw[base];
                bh[j][1] = KHw[base + 4];
                bl[j][0] = KLw[base];
                bl[j][1] = KLw[base + 4];
            }
#pragma unroll
            for (int mi = 0; mi < 2; mi++)
#pragma unroll
                for (int j = 0; j < 4; j++) {
                    mma16bf(sacc[mi][j], ah[mi], bh[j]);
                    mma16bf(sacc[mi][j], ah[mi], bl[j]);
                    mma16bf(sacc[mi][j], al[mi], bh[j]);
                }
        }

        const bool dg = (kt >= 2 * qb);
#pragma unroll
        for (int mi = 0; mi < 2; mi++) {
#pragma unroll
            for (int j = 0; j < 4; j++) {
                int rl0 = m0 + mi * 16 + gr;
                int cl  = wn + j * 8 + 2 * tc;
                float v0 = sacc[mi][j][0] * scale;
                float v1 = sacc[mi][j][1] * scale;
                float v2 = sacc[mi][j][2] * scale;
                float v3 = sacc[mi][j][3] * scale;
                if (dg) {
                    int rg0 = qb * 128 + rl0;
                    int cg  = kt * 64 + cl;
                    if (cg     > rg0)     v0 = -1e30f;
                    if (cg + 1 > rg0)     v1 = -1e30f;
                    if (cg     > rg0 + 8) v2 = -1e30f;
                    if (cg + 1 > rg0 + 8) v3 = -1e30f;
                }
                *(float2*)&SS[rl0 * 68 + cl]       = make_float2(v0, v1);
                *(float2*)&SS[(rl0 + 8) * 68 + cl] = make_float2(v2, v3);
            }
        }
        __syncthreads();

        // ---- online softmax, 256 threads; write P as packed bf16x2 hi/lo ----
        {
            const int r  = tid & 127;
            const int hf = tid >> 7;
            const float4* srow = (const float4*)(SS + r * 68) + hf * 8;
            float4 sv[8];
            float pm = -1e30f;
#pragma unroll
            for (int jj = 0; jj < 8; jj++) {
                sv[jj] = srow[jj];
                pm = fmaxf(pm, fmaxf(fmaxf(sv[jj].x, sv[jj].y), fmaxf(sv[jj].z, sv[jj].w)));
            }
            PPAR[tid] = pm;
            __syncthreads();
            float mOld = rowM[r];
            float m = fmaxf(mOld, fmaxf(PPAR[r], PPAR[r + 128]));
            float l = 0.f;
            uint32_t* phh = PHB + r * 36 + hf * 16;
            uint32_t* pll = PLB + r * 36 + hf * 16;
#pragma unroll
            for (int jj = 0; jj < 8; jj++) {
                float p0 = __expf(sv[jj].x - m);
                float p1 = __expf(sv[jj].y - m);
                float p2 = __expf(sv[jj].z - m);
                float p3 = __expf(sv[jj].w - m);
                l += (p0 + p1) + (p2 + p3);
                uint32_t lo0, lo1;
                uint32_t h0 = packsplit(p0, p1, lo0);
                uint32_t h1 = packsplit(p2, p3, lo1);
                phh[2 * jj]     = h0;
                phh[2 * jj + 1] = h1;
                pll[2 * jj]     = lo0;
                pll[2 * jj + 1] = lo1;
            }
            PPAR[tid] = l;
            __syncthreads();
            if (tid < 128) {
                float alpha = __expf(mOld - m);
                rowL[r] = rowL[r] * alpha + (PPAR[r] + PPAR[r + 128]);
                rowM[r] = m;
                rowA[r] = alpha;
            }
        }
        __syncthreads();

        // ---- O = alpha*O + P V  (bf16x3) ----
#pragma unroll
        for (int mi = 0; mi < 2; mi++) {
            float am0 = rowA[m0 + mi * 16 + gr];
            float am1 = rowA[m0 + mi * 16 + gr + 8];
#pragma unroll
            for (int j = 0; j < 8; j++) {
                o[mi][j][0] *= am0; o[mi][j][1] *= am0;
                o[mi][j][2] *= am1; o[mi][j][3] *= am1;
            }
        }
#pragma unroll
        for (int ks = 0; ks < 4; ks++) {
            uint32_t aph[2][4], apl[2][4];
#pragma unroll
            for (int mi = 0; mi < 2; mi++) {
                int base = (m0 + mi * 16 + gr) * 36 + ks * 8 + tc;
                aph[mi][0] = PHB[base];
                aph[mi][1] = PHB[base + 8 * 36];
                aph[mi][2] = PHB[base + 4];
                aph[mi][3] = PHB[base + 8 * 36 + 4];
                apl[mi][0] = PLB[base];
                apl[mi][1] = PLB[base + 8 * 36];
                apl[mi][2] = PLB[base + 4];
                apl[mi][3] = PLB[base + 8 * 36 + 4];
            }
#pragma unroll
            for (int j = 0; j < 8; j++) {
                int base = (nv + j * 8 + gr) * 36 + ks * 8 + tc;
                uint32_t bh[2], bl[2];
                bh[0] = VTH[base];
                bh[1] = VTH[base + 4];
                bl[0] = VTL[base];
                bl[1] = VTL[base + 4];
#pragma unroll
                for (int mi = 0; mi < 2; mi++) {
                    mma16bf(o[mi][j], aph[mi], bh);
                    mma16bf(o[mi][j], aph[mi], bl);
                    mma16bf(o[mi][j], apl[mi], bh);
                }
            }
        }
    }

    // normalize + rna-round + K-PERMUTED (8-group) store
    const int p0 = (tc < 2) ? 4 * tc     : 4 * tc - 7;
    const int p1 = (tc < 2) ? 4 * tc + 2 : 4 * tc - 5;
#pragma unroll
    for (int mi = 0; mi < 2; mi++) {
        int rl0 = m0 + mi * 16 + gr;
        float inv0 = 1.f / rowL[rl0];
        float inv1 = 1.f / rowL[rl0 + 8];
        int rg0 = qb * 128 + rl0;
#pragma unroll
        for (int j = 0; j < 8; j++) {
            int gbase = h * HD + nv + j * 8;
            float* d0 = out + (size_t)rg0 * DM + gbase;
            float* d1 = out + (size_t)(rg0 + 8) * DM + gbase;
            d0[p0] = ftf32(o[mi][j][0] * inv0);
            d0[p1] = ftf32(o[mi][j][1] * inv0);
            d1[p0] = ftf32(o[mi][j][2] * inv1);
            d1[p1] = ftf32(o[mi][j][3] * inv1);
        }
    }
}

// ===========================================================================
// Host side
// ===========================================================================
extern "C" void kernel_launch(void* const* d_in, const int* in_sizes, int n_in,
                              void* d_out, int out_size)
{
    const float* x     = (const float*)d_in[0];
    const float* w_qkv = (const float*)d_in[2];
    const float* w_out = (const float*)d_in[3];
    float* out = (float*)d_out;

    float *qkv, *attn, *xp, *wqkvp, *woutp;
    cudaGetSymbolAddress((void**)&qkv,   g_qkv);
    cudaGetSymbolAddress((void**)&attn,  g_attn);
    cudaGetSymbolAddress((void**)&xp,    g_xp);
    cudaGetSymbolAddress((void**)&wqkvp, g_wqkvp);
    cudaGetSymbolAddress((void**)&woutp, g_woutp);

    cudaFuncSetAttribute(gemm_mma, cudaFuncAttributeMaxDynamicSharedMemorySize,
                         GEMM_SMEM_BYTES);
    cudaFuncSetAttribute(attn_mma_kernel, cudaFuncAttributeMaxDynamicSharedMemorySize,
                         ATT_SMEM);

    // 0) inv_freq table + permute/round GEMM operands
    init_invf_kernel<<<1, 64>>>();
    {
        int n8x = TT * DM / 8;
        perm_round_kernel<<<(n8x + 255) / 256, 256>>>((const float4*)x, (float4*)xp, n8x);
        int n8q = QKV_N * DM / 8;
        perm_round_kernel<<<(n8q + 255) / 256, 256>>>((const float4*)w_qkv, (float4*)wqkvp, n8q);
        int n8o = DM * DM / 8;
        perm_round_kernel<<<(n8o + 255) / 256, 256>>>((const float4*)w_out, (float4*)woutp, n8o);
    }

    // 1) QKV projection + fused RoPE/clamp epilogue
    {
        dim3 grid(QKV_N / 128, TT / 128);
        gemm_mma<<<grid, 256, GEMM_SMEM_BYTES>>>(xp, wqkvp, qkv, QKV_N, DM, 1);
    }

    // 2) Tensor-core flash attention (writes 8-group permuted + rounded)
    {
        dim3 grid(TT / 128, NH);
        attn_mma_kernel<<<grid, 256, ATT_SMEM>>>(attn);
    }

    // 3) Output projection
    {
        dim3 grid(DM / 128, TT / 128);
        gemm_mma<<<grid, 256, GEMM_SMEM_BYTES>>>(attn, woutp, out, DM, DM, 0);
    }
}

// round 16
// speedup vs baseline: 1.1610x; 1.0001x over previous
#include <cuda_runtime.h>
#include <cuda_bf16.h>
#include <math.h>
#include <stdint.h>

// Problem constants
#define TT      2048
#define DM      6144
#define NH      48
#define NKV     8
#define HD      128
#define QKV_N   8192
#define KV_OFF  DM
#define V_OFF   (DM + NKV*HD)
#define REP     (NH / NKV)
#define CLAMP_V 8.0f

// Scratch (static device globals)
__device__ float g_qkv[(size_t)TT * QKV_N];
__device__ float g_attn[(size_t)TT * DM];
__device__ float g_xp[(size_t)TT * DM];
__device__ float g_wqkvp[(size_t)QKV_N * DM];
__device__ float g_woutp[(size_t)DM * DM];
__device__ float g_invf[64];

// ===========================================================================
// Helpers
// ===========================================================================
__device__ __forceinline__ uint32_t smem_to_u32(const void* p) {
    uint32_t a;
    asm("{ .reg .u64 t; cvta.to.shared.u64 t, %1; cvt.u32.u64 %0, t; }"
        : "=r"(a) : "l"(p));
    return a;
}
__device__ __forceinline__ void cp16(uint32_t s, const void* g) {
    asm volatile("cp.async.cg.shared.global [%0], [%1], 16;"
                 :: "r"(s), "l"(g) : "memory");
}
__device__ __forceinline__ float ftf32(float x) {
    uint32_t o, i = __float_as_uint(x);
    asm("cvt.rna.tf32.f32 %0, %1;" : "=r"(o) : "r"(i));
    return __uint_as_float(o);
}
__device__ __forceinline__ void mma8(float* d, const uint32_t* a, const uint32_t* b) {
    asm volatile(
        "mma.sync.aligned.m16n8k8.row.col.f32.tf32.tf32.f32 "
        "{%0,%1,%2,%3}, {%4,%5,%6,%7}, {%8,%9}, {%0,%1,%2,%3};"
        : "+f"(d[0]), "+f"(d[1]), "+f"(d[2]), "+f"(d[3])
        : "r"(a[0]), "r"(a[1]), "r"(a[2]), "r"(a[3]), "r"(b[0]), "r"(b[1]));
}
__device__ __forceinline__ void mma16bf(float* d, const uint32_t* a, const uint32_t* b) {
    asm volatile(
        "mma.sync.aligned.m16n8k16.row.col.f32.bf16.bf16.f32 "
        "{%0,%1,%2,%3}, {%4,%5,%6,%7}, {%8,%9}, {%0,%1,%2,%3};"
        : "+f"(d[0]), "+f"(d[1]), "+f"(d[2]), "+f"(d[3])
        : "r"(a[0]), "r"(a[1]), "r"(a[2]), "r"(a[3]), "r"(b[0]), "r"(b[1]));
}
__device__ __forceinline__ uint32_t packsplit(float x, float y, uint32_t& lo) {
    __nv_bfloat16 hx = __float2bfloat16(x);
    __nv_bfloat16 hy = __float2bfloat16(y);
    float rx = x - __bfloat162float(hx);
    float ry = y - __bfloat162float(hy);
    __nv_bfloat16 lx = __float2bfloat16(rx);
    __nv_bfloat16 ly = __float2bfloat16(ry);
    lo = ((uint32_t)__bfloat16_as_ushort(ly) << 16) | __bfloat16_as_ushort(lx);
    return ((uint32_t)__bfloat16_as_ushort(hy) << 16) | __bfloat16_as_ushort(hx);
}
__device__ __forceinline__ float clmp(float v) {
    return fminf(fmaxf(v, -CLAMP_V), CLAMP_V);
}

// ===========================================================================
// inv_freq table
// ===========================================================================
__global__ void init_invf_kernel()
{
    int i = threadIdx.x;
    g_invf[i] = (float)pow(500000.0, -(double)i / 64.0);
}

// ===========================================================================
// Permute (within-8 interleave [0,4,1,5,2,6,3,7]) + rna-tf32 round.
// ===========================================================================
__global__ __launch_bounds__(256)
void perm_round_kernel(const float4* __restrict__ src, float4* __restrict__ dst, int n8)
{
    int g = blockIdx.x * blockDim.x + threadIdx.x;
    if (g < n8) {
        float4 i0 = src[2 * g];
        float4 i1 = src[2 * g + 1];
        float4 o0 = make_float4(ftf32(i0.x), ftf32(i1.x), ftf32(i0.y), ftf32(i1.y));
        float4 o1 = make_float4(ftf32(i0.z), ftf32(i1.z), ftf32(i0.w), ftf32(i1.w));
        dst[2 * g]     = o0;
        dst[2 * g + 1] = o1;
    }
}

// ===========================================================================
// tf32 mma.sync GEMM (R12/R15 winner, unchanged).
// ===========================================================================
#define TSZ  (128 * 32)
#define GEMM_SMEM_BYTES (6 * TSZ * 4)

__global__ __launch_bounds__(256, 2)
void gemm_mma(const float* __restrict__ A, const float* __restrict__ B,
              float* __restrict__ C, int N, int K, int mode)
{
    extern __shared__ float sm[];
    const int tid  = threadIdx.x;
    const int wid  = tid >> 5, lane = tid & 31;
    const int wm   = (wid >> 2) * 64;
    const int wn   = (wid & 3) * 32;
    const int gr   = lane >> 2, tc = lane & 3;
    const int bm   = blockIdx.y * 128, bn = blockIdx.x * 128;

    const int ldr = tid >> 3;
    const int ldu = tid & 7;

    const uint32_t sbase = smem_to_u32(sm);
    const int NS = K / 32;

    float acc[4][4][4];
#pragma unroll
    for (int i = 0; i < 4; i++)
#pragma unroll
        for (int j = 0; j < 4; j++)
#pragma unroll
            for (int r = 0; r < 4; r++) acc[i][j][r] = 0.f;

    const int lsw = (ldr & 3) << 1;
    const int lu  = (ldu ^ lsw) << 2;

    auto loadTiles = [&](int k0, int st) {
#pragma unroll
        for (int v = 0; v < 4; v++) {
            int row = ldr + v * 32;
            uint32_t sa = sbase + (uint32_t)(st * TSZ + row * 32 + lu) * 4;
            cp16(sa, A + (size_t)(bm + row) * K + k0 + ldu * 4);
            uint32_t sb = sbase + (uint32_t)(3 * TSZ + st * TSZ + row * 32 + lu) * 4;
            cp16(sb, B + (size_t)(bn + row) * K + k0 + ldu * 4);
        }
        asm volatile("cp.async.commit_group;" ::: "memory");
    };

    loadTiles(0, 0);
    loadTiles(32, 1);

    const int asw = (gr & 3) << 1;
    const int ain = 2 * (tc & 1);
    int uofs[4];
#pragma unroll
    for (int ks = 0; ks < 4; ks++) {
        int u = 2 * ks + (tc >> 1);
        uofs[ks] = ((u ^ asw) << 2) + ain;
    }
    int arow[4], brow[4];
#pragma unroll
    for (int i = 0; i < 4; i++) arow[i] = (wm + i * 16 + gr) * 32;
#pragma unroll
    for (int j = 0; j < 4; j++) brow[j] = (wn + j * 8 + gr) * 32;

    int st = 0;
    for (int s = 0; s < NS; s++) {
        asm volatile("cp.async.wait_group 1;" ::: "memory");
        __syncthreads();

        int nst = st + 2; if (nst >= 3) nst -= 3;
        if (s + 2 < NS) loadTiles((s + 2) * 32, nst);
        else asm volatile("cp.async.commit_group;" ::: "memory");

        const float* As_ = sm + st * TSZ;
        const float* Bs_ = sm + 3 * TSZ + st * TSZ;

        uint32_t afr[2][4][4], bfr[2][4][2];
        auto loadFrags = [&](int ks, uint32_t af[4][4], uint32_t bf[4][2]) {
            const int uof = uofs[ks];
#pragma unroll
            for (int i = 0; i < 4; i++) {
                const float* ap = As_ + arow[i] + uof;
                float2 alo = *(const float2*)(ap);
                float2 ahi = *(const float2*)(ap + 256);
                af[i][0] = __float_as_uint(alo.x);
                af[i][1] = __float_as_uint(ahi.x);
                af[i][2] = __float_as_uint(alo.y);
                af[i][3] = __float_as_uint(ahi.y);
            }
#pragma unroll
            for (int j = 0; j < 4; j++) {
                float2 bv = *(const float2*)(Bs_ + brow[j] + uof);
                bf[j][0] = __float_as_uint(bv.x);
                bf[j][1] = __float_as_uint(bv.y);
            }
        };

        loadFrags(0, afr[0], bfr[0]);
#pragma unroll
        for (int ks = 0; ks < 4; ks++) {
            if (ks < 3) loadFrags(ks + 1, afr[(ks + 1) & 1], bfr[(ks + 1) & 1]);
            uint32_t (*a)[4] = afr[ks & 1];
            uint32_t (*b)[2] = bfr[ks & 1];
#pragma unroll
            for (int i = 0; i < 4; i++)
#pragma unroll
                for (int j = 0; j < 4; j++)
                    mma8(acc[i][j], a[i], b[j]);
        }

        if (++st == 3) st = 0;
    }

#pragma unroll
    for (int i = 0; i < 4; i++) {
#pragma unroll
        for (int j = 0; j < 4; j++) {
            int r = bm + wm + i * 16 + gr;
            int c = bn + wn + j * 8 + tc * 2;
            float2 v0 = make_float2(acc[i][j][0], acc[i][j][1]);
            float2 v1 = make_float2(acc[i][j][2], acc[i][j][3]);
            if (mode == 1) {
                if (c < V_OFF) {
                    int i64 = (c >> 1) & 63;
                    float inv = g_invf[i64];
                    float s0, c0;
                    sincosf((float)r * inv, &s0, &c0);
                    float a0 = v0.x, b0 = v0.y;
                    v0.x = clmp(a0 * c0 - b0 * s0);
                    v0.y = clmp(a0 * s0 + b0 * c0);
                    float s1, c1;
                    sincosf((float)(r + 8) * inv, &s1, &c1);
                    float a1 = v1.x, b1 = v1.y;
                    v1.x = clmp(a1 * c1 - b1 * s1);
                    v1.y = clmp(a1 * s1 + b1 * c1);
                } else {
                    v0.x = clmp(v0.x); v0.y = clmp(v0.y);
                    v1.x = clmp(v1.x); v1.y = clmp(v1.y);
                }
            }
            *(float2*)&C[(size_t)r * N + c]       = v0;
            *(float2*)&C[(size_t)(r + 8) * N + c] = v1;
        }
    }
}

// ===========================================================================
// Tensor-core flash attention.
// R16: (1) V loaded pre-paired (16 float2/thread) and packsplit+STS'd
//      DIRECTLY transposed into VTH/VTL (VS buffer + transpose phase gone);
//      (2) rowM/rowL double-buffered by tile parity; PV threads compute
//      alpha locally from rowM_cur + MPAR -> outer barrier removed.
// 5 barriers/tile (was 6). Numerics bitwise identical to R15.
// ===========================================================================
#define A_QH   0
#define A_QL   34816
#define A_KH   69632
#define A_KL   87040
#define A_VTH  104448
#define A_VTL  122880
#define A_SS   141312
#define A_PHB  176128
#define A_PLB  194560
#define A_STAT 212992            // rowM[2][128], rowL[2][128], MPAR[256], LPAR[256]
#define ATT_SMEM 217088

__global__ __launch_bounds__(256, 1)
void attn_mma_kernel(float* __restrict__ out)
{
    extern __shared__ char smem[];
    uint32_t* QHw = (uint32_t*)(smem + A_QH);
    uint32_t* QLw = (uint32_t*)(smem + A_QL);
    uint32_t* KHw = (uint32_t*)(smem + A_KH);
    uint32_t* KLw = (uint32_t*)(smem + A_KL);
    uint32_t* VTH = (uint32_t*)(smem + A_VTH);
    uint32_t* VTL = (uint32_t*)(smem + A_VTL);
    float*    SS  = (float*)(smem + A_SS);
    uint32_t* PHB = (uint32_t*)(smem + A_PHB);
    uint32_t* PLB = (uint32_t*)(smem + A_PLB);
    float* rowM = (float*)(smem + A_STAT);     // [2][128]
    float* rowL = rowM + 256;                   // [2][128]
    float* MPAR = rowL + 256;                   // [256]
    float* LPAR = MPAR + 256;                   // [256]

    const int qb   = gridDim.x - 1 - blockIdx.x;
    const int h    = blockIdx.y;
    const int kh   = h / REP;
    const int tid  = threadIdx.x;
    const int wid  = tid >> 5, lane = tid & 31;
    const int gr   = lane >> 2, tc = lane & 3;
    const int m0   = (wid >> 1) * 32;
    const int wn   = (wid & 1) * 32;
    const int nv   = (wid & 1) * 64;
    const float scale = 0.088388347648318447f;

    // K load coords (8 float4 rows)
    const int krow0 = tid >> 5;             // + 8i
    const int kcol  = (tid & 31) * 4;
    // V load coords: pre-paired (pair vp, dim slots vds + 16j)
    const int vp  = tid >> 3;               // kv pair 0..31
    const int vds = (tid & 7) * 2;          // dim base 0..14

    {
        const float* qg = g_qkv + (size_t)(qb * 128) * QKV_N + h * HD;
#pragma unroll
        for (int i = 0; i < 16; i++) {
            int f = tid + i * 256;
            int r = f >> 5;
            int c = (f & 31) * 4;
            float4 v = *(const float4*)(qg + (size_t)r * QKV_N + c);
            uint32_t l0, l1;
            uint32_t h0 = packsplit(v.x, v.y, l0);
            uint32_t h1 = packsplit(v.z, v.w, l1);
            QHw[r * 68 + c / 2]     = h0;
            QHw[r * 68 + c / 2 + 1] = h1;
            QLw[r * 68 + c / 2]     = l0;
            QLw[r * 68 + c / 2 + 1] = l1;
        }
    }
    if (tid < 128) { rowM[tid] = -1e30f; rowL[tid] = 0.f; }   // buffer 0

    float o[2][8][4];
#pragma unroll
    for (int mi = 0; mi < 2; mi++)
#pragma unroll
        for (int j = 0; j < 8; j++)
#pragma unroll
            for (int r = 0; r < 4; r++) o[mi][j][r] = 0.f;

    // staged K/V registers + prefetch of tile 0
    float4 kreg[8];
    float2 vr0[8], vr1[8];
    auto ldkv = [&](int kt) {
        const float* kg = g_qkv + (size_t)(kt * 64) * QKV_N + KV_OFF + kh * HD;
        const float* vg = g_qkv + (size_t)(kt * 64) * QKV_N + V_OFF  + kh * HD;
#pragma unroll
        for (int i = 0; i < 8; i++)
            kreg[i] = *(const float4*)(kg + (size_t)(krow0 + 8 * i) * QKV_N + kcol);
        const float* vg0 = vg + (size_t)(2 * vp) * QKV_N;
        const float* vg1 = vg + (size_t)(2 * vp + 1) * QKV_N;
#pragma unroll
        for (int j = 0; j < 8; j++) {
            int d = vds + j * 16;
            vr0[j] = *(const float2*)(vg0 + d);
            vr1[j] = *(const float2*)(vg1 + d);
        }
    };
    ldkv(0);

    const int nkt = 2 * qb + 2;
    for (int kt = 0; kt < nkt; kt++) {
        float* rowMc = rowM + (kt & 1) * 128;
        float* rowMn = rowM + ((kt + 1) & 1) * 128;
        float* rowLc = rowL + (kt & 1) * 128;
        float* rowLn = rowL + ((kt + 1) & 1) * 128;

        __syncthreads();   // prev PV done before clobbering K / VTH/VTL

        // ---- STS: K split (rows) + V split-transposed (pairs) ----
#pragma unroll
        for (int i = 0; i < 8; i++) {
            int r = krow0 + 8 * i;
            uint32_t l0, l1;
            uint32_t h0 = packsplit(kreg[i].x, kreg[i].y, l0);
            uint32_t h1 = packsplit(kreg[i].z, kreg[i].w, l1);
            KHw[r * 68 + kcol / 2]     = h0;
            KHw[r * 68 + kcol / 2 + 1] = h1;
            KLw[r * 68 + kcol / 2]     = l0;
            KLw[r * 68 + kcol / 2 + 1] = l1;
        }
#pragma unroll
        for (int j = 0; j < 8; j++) {
            int d = vds + j * 16;
            uint32_t lo0, lo1;
            uint32_t h0 = packsplit(vr0[j].x, vr1[j].x, lo0);   // dim d, pair vp
            uint32_t h1 = packsplit(vr0[j].y, vr1[j].y, lo1);   // dim d+1
            VTH[d * 36 + vp]       = h0;
            VTL[d * 36 + vp]       = lo0;
            VTH[(d + 1) * 36 + vp] = h1;
            VTL[(d + 1) * 36 + vp] = lo1;
        }
        // ---- prefetch next tile ----
        if (kt + 1 < nkt) ldkv(kt + 1);
        __syncthreads();

        // ---- S = Q K^T (bf16x3) ----
        float sacc[2][4][4];
#pragma unroll
        for (int mi = 0; mi < 2; mi++)
#pragma unroll
            for (int j = 0; j < 4; j++)
#pragma unroll
                for (int r = 0; r < 4; r++) sacc[mi][j][r] = 0.f;

#pragma unroll
        for (int ks = 0; ks < 8; ks++) {
            uint32_t ah[2][4], al[2][4];
#pragma unroll
            for (int mi = 0; mi < 2; mi++) {
                int base = (m0 + mi * 16 + gr) * 68 + ks * 8 + tc;
                ah[mi][0] = QHw[base];
                ah[mi][1] = QHw[base + 8 * 68];
                ah[mi][2] = QHw[base + 4];
                ah[mi][3] = QHw[base + 8 * 68 + 4];
                al[mi][0] = QLw[base];
                al[mi][1] = QLw[base + 8 * 68];
                al[mi][2] = QLw[base + 4];
                al[mi][3] = QLw[base + 8 * 68 + 4];
            }
            uint32_t bh[4][2], bl[4][2];
#pragma unroll
            for (int j = 0; j < 4; j++) {
                int base = (wn + j * 8 + gr) * 68 + ks * 8 + tc;
                bh[j][0] = KHw[base];
                bh[j][1] = KHw[base + 4];
                bl[j][0] = KLw[base];
                bl[j][1] = KLw[base + 4];
            }
#pragma unroll
            for (int mi = 0; mi < 2; mi++)
#pragma unroll
                for (int j = 0; j < 4; j++) {
                    mma16bf(sacc[mi][j], ah[mi], bh[j]);
                    mma16bf(sacc[mi][j], ah[mi], bl[j]);
                    mma16bf(sacc[mi][j], al[mi], bh[j]);
                }
        }

        const bool dg = (kt >= 2 * qb);
#pragma unroll
        for (int mi = 0; mi < 2; mi++) {
#pragma unroll
            for (int j = 0; j < 4; j++) {
                int rl0 = m0 + mi * 16 + gr;
                int cl  = wn + j * 8 + 2 * tc;
                float v0 = sacc[mi][j][0] * scale;
                float v1 = sacc[mi][j][1] * scale;
                float v2 = sacc[mi][j][2] * scale;
                float v3 = sacc[mi][j][3] * scale;
                if (dg) {
                    int rg0 = qb * 128 + rl0;
                    int cg  = kt * 64 + cl;
                    if (cg     > rg0)     v0 = -1e30f;
                    if (cg + 1 > rg0)     v1 = -1e30f;
                    if (cg     > rg0 + 8) v2 = -1e30f;
                    if (cg + 1 > rg0 + 8) v3 = -1e30f;
                }
                *(float2*)&SS[rl0 * 68 + cl]       = make_float2(v0, v1);
                *(float2*)&SS[(rl0 + 8) * 68 + cl] = make_float2(v2, v3);
            }
        }
        __syncthreads();

        // ---- online softmax (2 threads/row); no barrier after state update ----
        {
            const int r  = tid & 127;
            const int hf = tid >> 7;
            const float4* srow = (const float4*)(SS + r * 68) + hf * 8;
            float4 sv[8];
            float pm = -1e30f;
#pragma unroll
            for (int jj = 0; jj < 8; jj++) {
                sv[jj] = srow[jj];
                pm = fmaxf(pm, fmaxf(fmaxf(sv[jj].x, sv[jj].y), fmaxf(sv[jj].z, sv[jj].w)));
            }
            MPAR[tid] = pm;
            __syncthreads();
            float mOld = rowMc[r];
            float m = fmaxf(mOld, fmaxf(MPAR[r], MPAR[r + 128]));
            float l = 0.f;
            uint32_t* phh = PHB + r * 36 + hf * 16;
            uint32_t* pll = PLB + r * 36 + hf * 16;
#pragma unroll
            for (int jj = 0; jj < 8; jj++) {
                float p0 = __expf(sv[jj].x - m);
                float p1 = __expf(sv[jj].y - m);
                float p2 = __expf(sv[jj].z - m);
                float p3 = __expf(sv[jj].w - m);
                l += (p0 + p1) + (p2 + p3);
                uint32_t lo0, lo1;
                uint32_t h0 = packsplit(p0, p1, lo0);
                uint32_t h1 = packsplit(p2, p3, lo1);
                phh[2 * jj]     = h0;
                phh[2 * jj + 1] = h1;
                pll[2 * jj]     = lo0;
                pll[2 * jj + 1] = lo1;
            }
            LPAR[tid] = l;
            __syncthreads();
            if (tid < 128) {
                float alpha = __expf(mOld - m);
                rowLn[r] = rowLc[r] * alpha + (LPAR[r] + LPAR[r + 128]);
                rowMn[r] = m;
            }
        }
        // (no barrier: PV computes alpha locally; rowMn/rowLn are the other buffer)

        // ---- O = alpha*O + P V  (bf16x3) ----
#pragma unroll
        for (int mi = 0; mi < 2; mi++) {
            int r0 = m0 + mi * 16 + gr;
            float mo0 = rowMc[r0];
            float m0r = fmaxf(mo0, fmaxf(MPAR[r0], MPAR[r0 + 128]));
            float am0 = __expf(mo0 - m0r);
            int r1 = r0 + 8;
            float mo1 = rowMc[r1];
            float m1r = fmaxf(mo1, fmaxf(MPAR[r1], MPAR[r1 + 128]));
            float am1 = __expf(mo1 - m1r);
#pragma unroll
            for (int j = 0; j < 8; j++) {
                o[mi][j][0] *= am0; o[mi][j][1] *= am0;
                o[mi][j][2] *= am1; o[mi][j][3] *= am1;
            }
        }
#pragma unroll
        for (int ks = 0; ks < 4; ks++) {
            uint32_t aph[2][4], apl[2][4];
#pragma unroll
            for (int mi = 0; mi < 2; mi++) {
                int base = (m0 + mi * 16 + gr) * 36 + ks * 8 + tc;
                aph[mi][0] = PHB[base];
                aph[mi][1] = PHB[base + 8 * 36];
                aph[mi][2] = PHB[base + 4];
                aph[mi][3] = PHB[base + 8 * 36 + 4];
                apl[mi][0] = PLB[base];
                apl[mi][1] = PLB[base + 8 * 36];
                apl[mi][2] = PLB[base + 4];
                apl[mi][3] = PLB[base + 8 * 36 + 4];
            }
#pragma unroll
            for (int j = 0; j < 8; j++) {
                int base = (nv + j * 8 + gr) * 36 + ks * 8 + tc;
                uint32_t bh[2], bl[2];
                bh[0] = VTH[base];
                bh[1] = VTH[base + 4];
                bl[0] = VTL[base];
                bl[1] = VTL[base + 4];
#pragma unroll
                for (int mi = 0; mi < 2; mi++) {
                    mma16bf(o[mi][j], aph[mi], bh);
                    mma16bf(o[mi][j], aph[mi], bl);
                    mma16bf(o[mi][j], apl[mi], bh);
                }
            }
        }
    }

    // normalize + rna-round + K-PERMUTED (8-group) store
    // freshest rowL is in buffer nkt&1 == 0 (nkt even)
    __syncthreads();
    const float* rowLf = rowL + (nkt & 1) * 128;
    const int p0 = (tc < 2) ? 4 * tc     : 4 * tc - 7;
    const int p1 = (tc < 2) ? 4 * tc + 2 : 4 * tc - 5;
#pragma unroll
    for (int mi = 0; mi < 2; mi++) {
        int rl0 = m0 + mi * 16 + gr;
        float inv0 = 1.f / rowLf[rl0];
        float inv1 = 1.f / rowLf[rl0 + 8];
        int rg0 = qb * 128 + rl0;
#pragma unroll
        for (int j = 0; j < 8; j++) {
            int gbase = h * HD + nv + j * 8;
            float* d0 = out + (size_t)rg0 * DM + gbase;
            float* d1 = out + (size_t)(rg0 + 8) * DM + gbase;
            d0[p0] = ftf32(o[mi][j][0] * inv0);
            d0[p1] = ftf32(o[mi][j][1] * inv0);
            d1[p0] = ftf32(o[mi][j][2] * inv1);
            d1[p1] = ftf32(o[mi][j][3] * inv1);
        }
    }
}

// ===========================================================================
// Host side
// ===========================================================================
extern "C" void kernel_launch(void* const* d_in, const int* in_sizes, int n_in,
                              void* d_out, int out_size)
{
    const float* x     = (const float*)d_in[0];
    const float* w_qkv = (const float*)d_in[2];
    const float* w_out = (const float*)d_in[3];
    float* out = (float*)d_out;

    float *qkv, *attn, *xp, *wqkvp, *woutp;
    cudaGetSymbolAddress((void**)&qkv,   g_qkv);
    cudaGetSymbolAddress((void**)&attn,  g_attn);
    cudaGetSymbolAddress((void**)&xp,    g_xp);
    cudaGetSymbolAddress((void**)&wqkvp, g_wqkvp);
    cudaGetSymbolAddress((void**)&woutp, g_woutp);

    cudaFuncSetAttribute(gemm_mma, cudaFuncAttributeMaxDynamicSharedMemorySize,
                         GEMM_SMEM_BYTES);
    cudaFuncSetAttribute(attn_mma_kernel, cudaFuncAttributeMaxDynamicSharedMemorySize,
                         ATT_SMEM);

    // 0) inv_freq table + permute/round GEMM operands
    init_invf_kernel<<<1, 64>>>();
    {
        int n8x = TT * DM / 8;
        perm_round_kernel<<<(n8x + 255) / 256, 256>>>((const float4*)x, (float4*)xp, n8x);
        int n8q = QKV_N * DM / 8;
        perm_round_kernel<<<(n8q + 255) / 256, 256>>>((const float4*)w_qkv, (float4*)wqkvp, n8q);
        int n8o = DM * DM / 8;
        perm_round_kernel<<<(n8o + 255) / 256, 256>>>((const float4*)w_out, (float4*)woutp, n8o);
    }

    // 1) QKV projection + fused RoPE/clamp epilogue
    {
        dim3 grid(QKV_N / 128, TT / 128);
        gemm_mma<<<grid, 256, GEMM_SMEM_BYTES>>>(xp, wqkvp, qkv, QKV_N, DM, 1);
    }

    // 2) Tensor-core flash attention (writes 8-group permuted + rounded)
    {
        dim3 grid(TT / 128, NH);
        attn_mma_kernel<<<grid, 256, ATT_SMEM>>>(attn);
    }

    // 3) Output projection
    {
        dim3 grid(DM / 128, TT / 128);
        gemm_mma<<<grid, 256, GEMM_SMEM_BYTES>>>(attn, woutp, out, DM, DM, 0);
    }
}

// round 17
// speedup vs baseline: 1.1611x; 1.0002x over previous
#include <cuda_runtime.h>
#include <cuda_bf16.h>
#include <math.h>
#include <stdint.h>

// Problem constants
#define TT      2048
#define DM      6144
#define NH      48
#define NKV     8
#define HD      128
#define QKV_N   8192
#define KV_OFF  DM
#define V_OFF   (DM + NKV*HD)
#define REP     (NH / NKV)
#define CLAMP_V 8.0f

// Scratch (static device globals)
__device__ float g_qkv[(size_t)TT * QKV_N];
__device__ float g_attn[(size_t)TT * DM];
__device__ float g_xp[(size_t)TT * DM];
__device__ float g_wqkvp[(size_t)QKV_N * DM];
__device__ float g_woutp[(size_t)DM * DM];
__device__ float g_invf[64];

// ===========================================================================
// Helpers
// ===========================================================================
__device__ __forceinline__ uint32_t smem_to_u32(const void* p) {
    uint32_t a;
    asm("{ .reg .u64 t; cvta.to.shared.u64 t, %1; cvt.u32.u64 %0, t; }"
        : "=r"(a) : "l"(p));
    return a;
}
__device__ __forceinline__ void cp16(uint32_t s, const void* g) {
    asm volatile("cp.async.cg.shared.global [%0], [%1], 16;"
                 :: "r"(s), "l"(g) : "memory");
}
__device__ __forceinline__ float ftf32(float x) {
    uint32_t o, i = __float_as_uint(x);
    asm("cvt.rna.tf32.f32 %0, %1;" : "=r"(o) : "r"(i));
    return __uint_as_float(o);
}
__device__ __forceinline__ void mma8(float* d, const uint32_t* a, const uint32_t* b) {
    asm volatile(
        "mma.sync.aligned.m16n8k8.row.col.f32.tf32.tf32.f32 "
        "{%0,%1,%2,%3}, {%4,%5,%6,%7}, {%8,%9}, {%0,%1,%2,%3};"
        : "+f"(d[0]), "+f"(d[1]), "+f"(d[2]), "+f"(d[3])
        : "r"(a[0]), "r"(a[1]), "r"(a[2]), "r"(a[3]), "r"(b[0]), "r"(b[1]));
}
__device__ __forceinline__ void mma16bf(float* d, const uint32_t* a, const uint32_t* b) {
    asm volatile(
        "mma.sync.aligned.m16n8k16.row.col.f32.bf16.bf16.f32 "
        "{%0,%1,%2,%3}, {%4,%5,%6,%7}, {%8,%9}, {%0,%1,%2,%3};"
        : "+f"(d[0]), "+f"(d[1]), "+f"(d[2]), "+f"(d[3])
        : "r"(a[0]), "r"(a[1]), "r"(a[2]), "r"(a[3]), "r"(b[0]), "r"(b[1]));
}
__device__ __forceinline__ uint32_t packsplit(float x, float y, uint32_t& lo) {
    __nv_bfloat16 hx = __float2bfloat16(x);
    __nv_bfloat16 hy = __float2bfloat16(y);
    float rx = x - __bfloat162float(hx);
    float ry = y - __bfloat162float(hy);
    __nv_bfloat16 lx = __float2bfloat16(rx);
    __nv_bfloat16 ly = __float2bfloat16(ry);
    lo = ((uint32_t)__bfloat16_as_ushort(ly) << 16) | __bfloat16_as_ushort(lx);
    return ((uint32_t)__bfloat16_as_ushort(hy) << 16) | __bfloat16_as_ushort(hx);
}
__device__ __forceinline__ float clmp(float v) {
    return fminf(fmaxf(v, -CLAMP_V), CLAMP_V);
}

// ===========================================================================
// R17: merged preamble — one launch does all three permute+round passes
// (x, w_qkv, w_out) plus the inv_freq table. Same per-element math as the
// separate kernels -> bit-identical outputs.
// ===========================================================================
#define N8X  (TT * DM / 8)            // 1572864
#define N8Q  (QKV_N * DM / 8)         // 6291456
#define N8O  (DM * DM / 8)            // 4718592
#define N8ALL (N8X + N8Q + N8O)

__global__ __launch_bounds__(256)
void perm_round_all_kernel(const float4* __restrict__ x,
                           const float4* __restrict__ wq,
                           const float4* __restrict__ wo)
{
    if (blockIdx.x == 0 && threadIdx.x < 64) {
        int i = threadIdx.x;
        g_invf[i] = (float)pow(500000.0, -(double)i / 64.0);
    }

    float4* xp; float4* qp; float4* op;
    {
        // symbol addresses via inline (device-side) pointers
        xp = (float4*)g_xp; qp = (float4*)g_wqkvp; op = (float4*)g_woutp;
    }

    const int stride = gridDim.x * blockDim.x;
    for (int g = blockIdx.x * blockDim.x + threadIdx.x; g < N8ALL; g += stride) {
        const float4* src;
        float4* dst;
        int gg;
        if (g < N8X)            { src = x;  dst = xp; gg = g; }
        else if (g < N8X + N8Q) { src = wq; dst = qp; gg = g - N8X; }
        else                    { src = wo; dst = op; gg = g - N8X - N8Q; }
        float4 i0 = src[2 * gg];
        float4 i1 = src[2 * gg + 1];
        float4 o0 = make_float4(ftf32(i0.x), ftf32(i1.x), ftf32(i0.y), ftf32(i1.y));
        float4 o1 = make_float4(ftf32(i0.z), ftf32(i1.z), ftf32(i0.w), ftf32(i1.w));
        dst[2 * gg]     = o0;
        dst[2 * gg + 1] = o1;
    }
}

// ===========================================================================
// tf32 mma.sync GEMM (R12/R15 winner, unchanged).
// ===========================================================================
#define TSZ  (128 * 32)
#define GEMM_SMEM_BYTES (6 * TSZ * 4)

__global__ __launch_bounds__(256, 2)
void gemm_mma(const float* __restrict__ A, const float* __restrict__ B,
              float* __restrict__ C, int N, int K, int mode)
{
    extern __shared__ float sm[];
    const int tid  = threadIdx.x;
    const int wid  = tid >> 5, lane = tid & 31;
    const int wm   = (wid >> 2) * 64;
    const int wn   = (wid & 3) * 32;
    const int gr   = lane >> 2, tc = lane & 3;
    const int bm   = blockIdx.y * 128, bn = blockIdx.x * 128;

    const int ldr = tid >> 3;
    const int ldu = tid & 7;

    const uint32_t sbase = smem_to_u32(sm);
    const int NS = K / 32;

    float acc[4][4][4];
#pragma unroll
    for (int i = 0; i < 4; i++)
#pragma unroll
        for (int j = 0; j < 4; j++)
#pragma unroll
            for (int r = 0; r < 4; r++) acc[i][j][r] = 0.f;

    const int lsw = (ldr & 3) << 1;
    const int lu  = (ldu ^ lsw) << 2;

    auto loadTiles = [&](int k0, int st) {
#pragma unroll
        for (int v = 0; v < 4; v++) {
            int row = ldr + v * 32;
            uint32_t sa = sbase + (uint32_t)(st * TSZ + row * 32 + lu) * 4;
            cp16(sa, A + (size_t)(bm + row) * K + k0 + ldu * 4);
            uint32_t sb = sbase + (uint32_t)(3 * TSZ + st * TSZ + row * 32 + lu) * 4;
            cp16(sb, B + (size_t)(bn + row) * K + k0 + ldu * 4);
        }
        asm volatile("cp.async.commit_group;" ::: "memory");
    };

    loadTiles(0, 0);
    loadTiles(32, 1);

    const int asw = (gr & 3) << 1;
    const int ain = 2 * (tc & 1);
    int uofs[4];
#pragma unroll
    for (int ks = 0; ks < 4; ks++) {
        int u = 2 * ks + (tc >> 1);
        uofs[ks] = ((u ^ asw) << 2) + ain;
    }
    int arow[4], brow[4];
#pragma unroll
    for (int i = 0; i < 4; i++) arow[i] = (wm + i * 16 + gr) * 32;
#pragma unroll
    for (int j = 0; j < 4; j++) brow[j] = (wn + j * 8 + gr) * 32;

    int st = 0;
    for (int s = 0; s < NS; s++) {
        asm volatile("cp.async.wait_group 1;" ::: "memory");
        __syncthreads();

        int nst = st + 2; if (nst >= 3) nst -= 3;
        if (s + 2 < NS) loadTiles((s + 2) * 32, nst);
        else asm volatile("cp.async.commit_group;" ::: "memory");

        const float* As_ = sm + st * TSZ;
        const float* Bs_ = sm + 3 * TSZ + st * TSZ;

        uint32_t afr[2][4][4], bfr[2][4][2];
        auto loadFrags = [&](int ks, uint32_t af[4][4], uint32_t bf[4][2]) {
            const int uof = uofs[ks];
#pragma unroll
            for (int i = 0; i < 4; i++) {
                const float* ap = As_ + arow[i] + uof;
                float2 alo = *(const float2*)(ap);
                float2 ahi = *(const float2*)(ap + 256);
                af[i][0] = __float_as_uint(alo.x);
                af[i][1] = __float_as_uint(ahi.x);
                af[i][2] = __float_as_uint(alo.y);
                af[i][3] = __float_as_uint(ahi.y);
            }
#pragma unroll
            for (int j = 0; j < 4; j++) {
                float2 bv = *(const float2*)(Bs_ + brow[j] + uof);
                bf[j][0] = __float_as_uint(bv.x);
                bf[j][1] = __float_as_uint(bv.y);
            }
        };

        loadFrags(0, afr[0], bfr[0]);
#pragma unroll
        for (int ks = 0; ks < 4; ks++) {
            if (ks < 3) loadFrags(ks + 1, afr[(ks + 1) & 1], bfr[(ks + 1) & 1]);
            uint32_t (*a)[4] = afr[ks & 1];
            uint32_t (*b)[2] = bfr[ks & 1];
#pragma unroll
            for (int i = 0; i < 4; i++)
#pragma unroll
                for (int j = 0; j < 4; j++)
                    mma8(acc[i][j], a[i], b[j]);
        }

        if (++st == 3) st = 0;
    }

#pragma unroll
    for (int i = 0; i < 4; i++) {
#pragma unroll
        for (int j = 0; j < 4; j++) {
            int r = bm + wm + i * 16 + gr;
            int c = bn + wn + j * 8 + tc * 2;
            float2 v0 = make_float2(acc[i][j][0], acc[i][j][1]);
            float2 v1 = make_float2(acc[i][j][2], acc[i][j][3]);
            if (mode == 1) {
                if (c < V_OFF) {
                    int i64 = (c >> 1) & 63;
                    float inv = g_invf[i64];
                    float s0, c0;
                    sincosf((float)r * inv, &s0, &c0);
                    float a0 = v0.x, b0 = v0.y;
                    v0.x = clmp(a0 * c0 - b0 * s0);
                    v0.y = clmp(a0 * s0 + b0 * c0);
                    float s1, c1;
                    sincosf((float)(r + 8) * inv, &s1, &c1);
                    float a1 = v1.x, b1 = v1.y;
                    v1.x = clmp(a1 * c1 - b1 * s1);
                    v1.y = clmp(a1 * s1 + b1 * c1);
                } else {
                    v0.x = clmp(v0.x); v0.y = clmp(v0.y);
                    v1.x = clmp(v1.x); v1.y = clmp(v1.y);
                }
            }
            *(float2*)&C[(size_t)r * N + c]       = v0;
            *(float2*)&C[(size_t)(r + 8) * N + c] = v1;
        }
    }
}

// ===========================================================================
// Tensor-core flash attention (R16 winner, unchanged).
// ===========================================================================
#define A_QH   0
#define A_QL   34816
#define A_KH   69632
#define A_KL   87040
#define A_VTH  104448
#define A_VTL  122880
#define A_SS   141312
#define A_PHB  176128
#define A_PLB  194560
#define A_STAT 212992
#define ATT_SMEM 217088

__global__ __launch_bounds__(256, 1)
void attn_mma_kernel(float* __restrict__ out)
{
    extern __shared__ char smem[];
    uint32_t* QHw = (uint32_t*)(smem + A_QH);
    uint32_t* QLw = (uint32_t*)(smem + A_QL);
    uint32_t* KHw = (uint32_t*)(smem + A_KH);
    uint32_t* KLw = (uint32_t*)(smem + A_KL);
    uint32_t* VTH = (uint32_t*)(smem + A_VTH);
    uint32_t* VTL = (uint32_t*)(smem + A_VTL);
    float*    SS  = (float*)(smem + A_SS);
    uint32_t* PHB = (uint32_t*)(smem + A_PHB);
    uint32_t* PLB = (uint32_t*)(smem + A_PLB);
    float* rowM = (float*)(smem + A_STAT);
    float* rowL = rowM + 256;
    float* MPAR = rowL + 256;
    float* LPAR = MPAR + 256;

    const int qb   = gridDim.x - 1 - blockIdx.x;
    const int h    = blockIdx.y;
    const int kh   = h / REP;
    const int tid  = threadIdx.x;
    const int wid  = tid >> 5, lane = tid & 31;
    const int gr   = lane >> 2, tc = lane & 3;
    const int m0   = (wid >> 1) * 32;
    const int wn   = (wid & 1) * 32;
    const int nv   = (wid & 1) * 64;
    const float scale = 0.088388347648318447f;

    const int krow0 = tid >> 5;
    const int kcol  = (tid & 31) * 4;
    const int vp  = tid >> 3;
    const int vds = (tid & 7) * 2;

    {
        const float* qg = g_qkv + (size_t)(qb * 128) * QKV_N + h * HD;
#pragma unroll
        for (int i = 0; i < 16; i++) {
            int f = tid + i * 256;
            int r = f >> 5;
            int c = (f & 31) * 4;
            float4 v = *(const float4*)(qg + (size_t)r * QKV_N + c);
            uint32_t l0, l1;
            uint32_t h0 = packsplit(v.x, v.y, l0);
            uint32_t h1 = packsplit(v.z, v.w, l1);
            QHw[r * 68 + c / 2]     = h0;
            QHw[r * 68 + c / 2 + 1] = h1;
            QLw[r * 68 + c / 2]     = l0;
            QLw[r * 68 + c / 2 + 1] = l1;
        }
    }
    if (tid < 128) { rowM[tid] = -1e30f; rowL[tid] = 0.f; }

    float o[2][8][4];
#pragma unroll
    for (int mi = 0; mi < 2; mi++)
#pragma unroll
        for (int j = 0; j < 8; j++)
#pragma unroll
            for (int r = 0; r < 4; r++) o[mi][j][r] = 0.f;

    float4 kreg[8];
    float2 vr0[8], vr1[8];
    auto ldkv = [&](int kt) {
        const float* kg = g_qkv + (size_t)(kt * 64) * QKV_N + KV_OFF + kh * HD;
        const float* vg = g_qkv + (size_t)(kt * 64) * QKV_N + V_OFF  + kh * HD;
#pragma unroll
        for (int i = 0; i < 8; i++)
            kreg[i] = *(const float4*)(kg + (size_t)(krow0 + 8 * i) * QKV_N + kcol);
        const float* vg0 = vg + (size_t)(2 * vp) * QKV_N;
        const float* vg1 = vg + (size_t)(2 * vp + 1) * QKV_N;
#pragma unroll
        for (int j = 0; j < 8; j++) {
            int d = vds + j * 16;
            vr0[j] = *(const float2*)(vg0 + d);
            vr1[j] = *(const float2*)(vg1 + d);
        }
    };
    ldkv(0);

    const int nkt = 2 * qb + 2;
    for (int kt = 0; kt < nkt; kt++) {
        float* rowMc = rowM + (kt & 1) * 128;
        float* rowMn = rowM + ((kt + 1) & 1) * 128;
        float* rowLc = rowL + (kt & 1) * 128;
        float* rowLn = rowL + ((kt + 1) & 1) * 128;

        __syncthreads();

#pragma unroll
        for (int i = 0; i < 8; i++) {
            int r = krow0 + 8 * i;
            uint32_t l0, l1;
            uint32_t h0 = packsplit(kreg[i].x, kreg[i].y, l0);
            uint32_t h1 = packsplit(kreg[i].z, kreg[i].w, l1);
            KHw[r * 68 + kcol / 2]     = h0;
            KHw[r * 68 + kcol / 2 + 1] = h1;
            KLw[r * 68 + kcol / 2]     = l0;
            KLw[r * 68 + kcol / 2 + 1] = l1;
        }
#pragma unroll
        for (int j = 0; j < 8; j++) {
            int d = vds + j * 16;
            uint32_t lo0, lo1;
            uint32_t h0 = packsplit(vr0[j].x, vr1[j].x, lo0);
            uint32_t h1 = packsplit(vr0[j].y, vr1[j].y, lo1);
            VTH[d * 36 + vp]       = h0;
            VTL[d * 36 + vp]       = lo0;
            VTH[(d + 1) * 36 + vp] = h1;
            VTL[(d + 1) * 36 + vp] = lo1;
        }
        if (kt + 1 < nkt) ldkv(kt + 1);
        __syncthreads();

        float sacc[2][4][4];
#pragma unroll
        for (int mi = 0; mi < 2; mi++)
#pragma unroll
            for (int j = 0; j < 4; j++)
#pragma unroll
                for (int r = 0; r < 4; r++) sacc[mi][j][r] = 0.f;

#pragma unroll
        for (int ks = 0; ks < 8; ks++) {
            uint32_t ah[2][4], al[2][4];
#pragma unroll
            for (int mi = 0; mi < 2; mi++) {
                int base = (m0 + mi * 16 + gr) * 68 + ks * 8 + tc;
                ah[mi][0] = QHw[base];
                ah[mi][1] = QHw[base + 8 * 68];
                ah[mi][2] = QHw[base + 4];
                ah[mi][3] = QHw[base + 8 * 68 + 4];
                al[mi][0] = QLw[base];
                al[mi][1] = QLw[base + 8 * 68];
                al[mi][2] = QLw[base + 4];
                al[mi][3] = QLw[base + 8 * 68 + 4];
            }
            uint32_t bh[4][2], bl[4][2];
#pragma unroll
            for (int j = 0; j < 4; j++) {
                int base = (wn + j * 8 + gr) * 68 + ks * 8 + tc;
                bh[j][0] = KHw[base];
                bh[j][1] = KHw[base + 4];
                bl[j][0] = KLw[base];
                bl[j][1] = KLw[base + 4];
            }
#pragma unroll
            for (int mi = 0; mi < 2; mi++)
#pragma unroll
                for (int j = 0; j < 4; j++) {
                    mma16bf(sacc[mi][j], ah[mi], bh[j]);
                    mma16bf(sacc[mi][j], ah[mi], bl[j]);
                    mma16bf(sacc[mi][j], al[mi], bh[j]);
                }
        }

        const bool dg = (kt >= 2 * qb);
#pragma unroll
        for (int mi = 0; mi < 2; mi++) {
#pragma unroll
            for (int j = 0; j < 4; j++) {
                int rl0 = m0 + mi * 16 + gr;
                int cl  = wn + j * 8 + 2 * tc;
                float v0 = sacc[mi][j][0] * scale;
                float v1 = sacc[mi][j][1] * scale;
                float v2 = sacc[mi][j][2] * scale;
                float v3 = sacc[mi][j][3] * scale;
                if (dg) {
                    int rg0 = qb * 128 + rl0;
                    int cg  = kt * 64 + cl;
                    if (cg     > rg0)     v0 = -1e30f;
                    if (cg + 1 > rg0)     v1 = -1e30f;
                    if (cg     > rg0 + 8) v2 = -1e30f;
                    if (cg + 1 > rg0 + 8) v3 = -1e30f;
                }
                *(float2*)&SS[rl0 * 68 + cl]       = make_float2(v0, v1);
                *(float2*)&SS[(rl0 + 8) * 68 + cl] = make_float2(v2, v3);
            }
        }
        __syncthreads();

        {
            const int r  = tid & 127;
            const int hf = tid >> 7;
            const float4* srow = (const float4*)(SS + r * 68) + hf * 8;
            float4 sv[8];
            float pm = -1e30f;
#pragma unroll
            for (int jj = 0; jj < 8; jj++) {
                sv[jj] = srow[jj];
                pm = fmaxf(pm, fmaxf(fmaxf(sv[jj].x, sv[jj].y), fmaxf(sv[jj].z, sv[jj].w)));
            }
            MPAR[tid] = pm;
            __syncthreads();
            float mOld = rowMc[r];
            float m = fmaxf(mOld, fmaxf(MPAR[r], MPAR[r + 128]));
            float l = 0.f;
            uint32_t* phh = PHB + r * 36 + hf * 16;
            uint32_t* pll = PLB + r * 36 + hf * 16;
#pragma unroll
            for (int jj = 0; jj < 8; jj++) {
                float p0 = __expf(sv[jj].x - m);
                float p1 = __expf(sv[jj].y - m);
                float p2 = __expf(sv[jj].z - m);
                float p3 = __expf(sv[jj].w - m);
                l += (p0 + p1) + (p2 + p3);
                uint32_t lo0, lo1;
                uint32_t h0 = packsplit(p0, p1, lo0);
                uint32_t h1 = packsplit(p2, p3, lo1);
                phh[2 * jj]     = h0;
                phh[2 * jj + 1] = h1;
                pll[2 * jj]     = lo0;
                pll[2 * jj + 1] = lo1;
            }
            LPAR[tid] = l;
            __syncthreads();
            if (tid < 128) {
                float alpha = __expf(mOld - m);
                rowLn[r] = rowLc[r] * alpha + (LPAR[r] + LPAR[r + 128]);
                rowMn[r] = m;
            }
        }

#pragma unroll
        for (int mi = 0; mi < 2; mi++) {
            int r0 = m0 + mi * 16 + gr;
            float mo0 = rowMc[r0];
            float m0r = fmaxf(mo0, fmaxf(MPAR[r0], MPAR[r0 + 128]));
            float am0 = __expf(mo0 - m0r);
            int r1 = r0 + 8;
            float mo1 = rowMc[r1];
            float m1r = fmaxf(mo1, fmaxf(MPAR[r1], MPAR[r1 + 128]));
            float am1 = __expf(mo1 - m1r);
#pragma unroll
            for (int j = 0; j < 8; j++) {
                o[mi][j][0] *= am0; o[mi][j][1] *= am0;
                o[mi][j][2] *= am1; o[mi][j][3] *= am1;
            }
        }
#pragma unroll
        for (int ks = 0; ks < 4; ks++) {
            uint32_t aph[2][4], apl[2][4];
#pragma unroll
            for (int mi = 0; mi < 2; mi++) {
                int base = (m0 + mi * 16 + gr) * 36 + ks * 8 + tc;
                aph[mi][0] = PHB[base];
                aph[mi][1] = PHB[base + 8 * 36];
                aph[mi][2] = PHB[base + 4];
                aph[mi][3] = PHB[base + 8 * 36 + 4];
                apl[mi][0] = PLB[base];
                apl[mi][1] = PLB[base + 8 * 36];
                apl[mi][2] = PLB[base + 4];
                apl[mi][3] = PLB[base + 8 * 36 + 4];
            }
#pragma unroll
            for (int j = 0; j < 8; j++) {
                int base = (nv + j * 8 + gr) * 36 + ks * 8 + tc;
                uint32_t bh[2], bl[2];
                bh[0] = VTH[base];
                bh[1] = VTH[base + 4];
                bl[0] = VTL[base];
                bl[1] = VTL[base + 4];
#pragma unroll
                for (int mi = 0; mi < 2; mi++) {
                    mma16bf(o[mi][j], aph[mi], bh);
                    mma16bf(o[mi][j], aph[mi], bl);
                    mma16bf(o[mi][j], apl[mi], bh);
                }
            }
        }
    }

    __syncthreads();
    const float* rowLf = rowL + (nkt & 1) * 128;
    const int p0 = (tc < 2) ? 4 * tc     : 4 * tc - 7;
    const int p1 = (tc < 2) ? 4 * tc + 2 : 4 * tc - 5;
#pragma unroll
    for (int mi = 0; mi < 2; mi++) {
        int rl0 = m0 + mi * 16 + gr;
        float inv0 = 1.f / rowLf[rl0];
        float inv1 = 1.f / rowLf[rl0 + 8];
        int rg0 = qb * 128 + rl0;
#pragma unroll
        for (int j = 0; j < 8; j++) {
            int gbase = h * HD + nv + j * 8;
            float* d0 = out + (size_t)rg0 * DM + gbase;
            float* d1 = out + (size_t)(rg0 + 8) * DM + gbase;
            d0[p0] = ftf32(o[mi][j][0] * inv0);
            d0[p1] = ftf32(o[mi][j][1] * inv0);
            d1[p0] = ftf32(o[mi][j][2] * inv1);
            d1[p1] = ftf32(o[mi][j][3] * inv1);
        }
    }
}

// ===========================================================================
// Host side
// ===========================================================================
extern "C" void kernel_launch(void* const* d_in, const int* in_sizes, int n_in,
                              void* d_out, int out_size)
{
    const float* x     = (const float*)d_in[0];
    const float* w_qkv = (const float*)d_in[2];
    const float* w_out = (const float*)d_in[3];
    float* out = (float*)d_out;

    float *qkv, *attn, *xp, *wqkvp, *woutp;
    cudaGetSymbolAddress((void**)&qkv,   g_qkv);
    cudaGetSymbolAddress((void**)&attn,  g_attn);
    cudaGetSymbolAddress((void**)&xp,    g_xp);
    cudaGetSymbolAddress((void**)&wqkvp, g_wqkvp);
    cudaGetSymbolAddress((void**)&woutp, g_woutp);

    cudaFuncSetAttribute(gemm_mma, cudaFuncAttributeMaxDynamicSharedMemorySize,
                         GEMM_SMEM_BYTES);
    cudaFuncSetAttribute(attn_mma_kernel, cudaFuncAttributeMaxDynamicSharedMemorySize,
                         ATT_SMEM);

    // 0) merged preamble: inv_freq table + all three permute/round passes
    {
        int blocks = 4736;   // 32 CTAs/SM wave; grid-stride covers N8ALL
        perm_round_all_kernel<<<blocks, 256>>>((const float4*)x,
                                               (const float4*)w_qkv,
                                               (const float4*)w_out);
    }

    // 1) QKV projection + fused RoPE/clamp epilogue
    {
        dim3 grid(QKV_N / 128, TT / 128);
        gemm_mma<<<grid, 256, GEMM_SMEM_BYTES>>>(xp, wqkvp, qkv, QKV_N, DM, 1);
    }

    // 2) Tensor-core flash attention (writes 8-group permuted + rounded)
    {
        dim3 grid(TT / 128, NH);
        attn_mma_kernel<<<grid, 256, ATT_SMEM>>>(attn);
    }

    // 3) Output projection
    {
        dim3 grid(DM / 128, TT / 128);
        gemm_mma<<<grid, 256, GEMM_SMEM_BYTES>>>(attn, woutp, out, DM, DM, 0);
    }
}